// round 1
// baseline (speedup 1.0000x reference)
#include <cuda_runtime.h>
#include <math.h>

#define Bb 64
#define Ll 256
#define DIN 768
#define MEMD 300
#define Hh 6
#define TOPK 1024
#define NCc 3
#define NLAYERS 2
#define DKk 50
#define BL (Bb*Ll)   // 16384

// ---------------- scratch (device globals; no runtime allocation) ----------------
__device__ float g_q[BL*DIN];                 // 50 MB
__device__ float g_k[BL*DIN];                 // 50 MB
__device__ float g_scores[Bb*Hh*Ll*Ll];       // 100 MB
__device__ float g_pattn[Bb*Ll*Ll];           // 16.8 MB
__device__ float g_kth[Bb];
__device__ unsigned char g_adj[Bb*Ll*Ll];     // 4.2 MB
__device__ float g_h[BL*MEMD];                // 19.7 MB
__device__ float g_proj[BL*MEMD];             // 19.7 MB
__device__ float g_cat[BL*MEMD];              // 19.7 MB
__device__ float g_si[Bb*Hh*Ll];
__device__ float g_sj[Bb*Hh*Ll];
__device__ float g_wcat[NLAYERS*MEMD*MEMD];   // repacked Wh

// ---------------- reduction helpers (256 threads) ----------------
__device__ __forceinline__ float warpSum(float v){
  #pragma unroll
  for(int o=16;o;o>>=1) v += __shfl_xor_sync(0xffffffffu, v, o);
  return v;
}
__device__ __forceinline__ float warpMax(float v){
  #pragma unroll
  for(int o=16;o;o>>=1) v = fmaxf(v, __shfl_xor_sync(0xffffffffu, v, o));
  return v;
}
__device__ __forceinline__ float blockSum256(float v, float* sh){
  v = warpSum(v);
  int w = threadIdx.x >> 5;
  if((threadIdx.x & 31) == 0) sh[w] = v;
  __syncthreads();
  if(threadIdx.x < 8){
    float x = sh[threadIdx.x];
    #pragma unroll
    for(int o=4;o;o>>=1) x += __shfl_xor_sync(0xffu, x, o);
    if(threadIdx.x==0) sh[0] = x;
  }
  __syncthreads();
  float r = sh[0];
  __syncthreads();
  return r;
}
__device__ __forceinline__ float blockMax256(float v, float* sh){
  v = warpMax(v);
  int w = threadIdx.x >> 5;
  if((threadIdx.x & 31) == 0) sh[w] = v;
  __syncthreads();
  if(threadIdx.x < 8){
    float x = sh[threadIdx.x];
    #pragma unroll
    for(int o=4;o;o>>=1) x = fmaxf(x, __shfl_xor_sync(0xffu, x, o));
    if(threadIdx.x==0) sh[0] = x;
  }
  __syncthreads();
  float r = sh[0];
  __syncthreads();
  return r;
}

// ---------------- SGEMM: C[M,N] = A[M,K] @ W[K,N] + bias[N] ----------------
// 128x128 tile, BK=8, 256 threads, 8x8 microtile. M must be multiple of 128.
__global__ __launch_bounds__(256) void sgemm128(
    const float* __restrict__ A, const float* __restrict__ W,
    const float* __restrict__ bias, float* __restrict__ C,
    int M, int N, int K)
{
  __shared__ __align__(16) float As[8][128];
  __shared__ __align__(16) float Ws[8][128];
  int tid = threadIdx.x;
  int tx = tid & 15, ty = tid >> 4;
  int row0 = blockIdx.y * 128, col0 = blockIdx.x * 128;
  float acc[8][8];
  #pragma unroll
  for(int i=0;i<8;i++)
    #pragma unroll
    for(int j=0;j<8;j++) acc[i][j]=0.f;

  for(int k0=0;k0<K;k0+=8){
    #pragma unroll
    for(int i=0;i<4;i++){
      int e = tid + i*256; int m = e >> 3, kk = e & 7;
      int gk = k0 + kk;
      As[kk][m] = (gk < K) ? A[(size_t)(row0+m)*K + gk] : 0.f;
    }
    #pragma unroll
    for(int i=0;i<4;i++){
      int e = tid + i*256; int kk = e >> 7, n = e & 127;
      int gk = k0 + kk, gc = col0 + n;
      Ws[kk][n] = (gk < K && gc < N) ? W[(size_t)gk*N + gc] : 0.f;
    }
    __syncthreads();
    #pragma unroll
    for(int kk=0;kk<8;kk++){
      float a[8], bv[8];
      *(float4*)(a)    = *(const float4*)&As[kk][ty*8];
      *(float4*)(a+4)  = *(const float4*)&As[kk][ty*8+4];
      *(float4*)(bv)   = *(const float4*)&Ws[kk][tx*8];
      *(float4*)(bv+4) = *(const float4*)&Ws[kk][tx*8+4];
      #pragma unroll
      for(int i=0;i<8;i++)
        #pragma unroll
        for(int j=0;j<8;j++) acc[i][j] = fmaf(a[i], bv[j], acc[i][j]);
    }
    __syncthreads();
  }
  #pragma unroll
  for(int i=0;i<8;i++){
    int gr = row0 + ty*8 + i;
    #pragma unroll
    for(int j=0;j<8;j++){
      int gc = col0 + tx*8 + j;
      if(gc < N) C[(size_t)gr*N + gc] = acc[i][j] + bias[gc];
    }
  }
}

// ---------------- QK^T scores, per (b,h): C[l,m] = q_h[l,:].k_h[m,:] / sqrt(128) ----------------
__global__ __launch_bounds__(256) void qk_scores_kernel(
    const float* __restrict__ q, const float* __restrict__ k, float* __restrict__ scores)
{
  int bh = blockIdx.y;
  int b = bh / Hh, h = bh - b*Hh;
  int lt = (blockIdx.x >> 2) * 64, mt = (blockIdx.x & 3) * 64;
  const float* qb = q + (size_t)b*Ll*DIN + h*128;
  const float* kb = k + (size_t)b*Ll*DIN + h*128;
  __shared__ __align__(16) float Qs[16][64];
  __shared__ __align__(16) float Ks[16][64];
  int tid = threadIdx.x, tx = tid & 15, ty = tid >> 4;
  float acc[4][4];
  #pragma unroll
  for(int i=0;i<4;i++)
    #pragma unroll
    for(int j=0;j<4;j++) acc[i][j]=0.f;

  for(int k0=0;k0<128;k0+=16){
    #pragma unroll
    for(int i=0;i<4;i++){
      int e = tid + i*256; int m = e >> 4, kk = e & 15;
      Qs[kk][m] = qb[(size_t)(lt+m)*DIN + k0 + kk];
      Ks[kk][m] = kb[(size_t)(mt+m)*DIN + k0 + kk];
    }
    __syncthreads();
    #pragma unroll
    for(int kk=0;kk<16;kk++){
      float a[4], bv[4];
      *(float4*)a  = *(const float4*)&Qs[kk][ty*4];
      *(float4*)bv = *(const float4*)&Ks[kk][tx*4];
      #pragma unroll
      for(int i=0;i<4;i++)
        #pragma unroll
        for(int j=0;j<4;j++) acc[i][j] = fmaf(a[i], bv[j], acc[i][j]);
    }
    __syncthreads();
  }
  const float scale = 0.08838834764831845f; // 1/sqrt(128)
  #pragma unroll
  for(int i=0;i<4;i++){
    int gl = lt + ty*4 + i;
    #pragma unroll
    for(int j=0;j<4;j++){
      int gm = mt + tx*4 + j;
      scores[((size_t)bh*Ll + gl)*Ll + gm] = acc[i][j] * scale;
    }
  }
}

// ---------------- softmax over m per (b,h,l), mean over heads -> p_attn ----------------
__global__ __launch_bounds__(256) void softmax_mean_kernel(
    const float* __restrict__ scores, float* __restrict__ pattn)
{
  __shared__ float red[8];
  int bl = blockIdx.x;
  int b = bl >> 8, l = bl & 255;
  int m = threadIdx.x;
  float acc = 0.f;
  for(int h=0; h<Hh; h++){
    float s = scores[(((size_t)(b*Hh+h))*Ll + l)*Ll + m];
    float mx = blockMax256(s, red);
    float e = expf(s - mx);
    float sm = blockSum256(e, red);
    acc += e / sm;
  }
  pattn[(size_t)bl*Ll + m] = acc * (1.f/6.f);
}

// ---------------- exact 1024th-largest per batch via radix select on float bits ----------------
__global__ __launch_bounds__(256) void topk_select_kernel(
    const float* __restrict__ pattn, float* __restrict__ kth)
{
  int b = blockIdx.x;
  int tid = threadIdx.x;
  const unsigned* v = (const unsigned*)(pattn + (size_t)b*Ll*Ll);
  __shared__ unsigned hist[256];
  __shared__ unsigned s_prefix;
  __shared__ int s_k;
  if(tid == 0){ s_prefix = 0u; s_k = TOPK; }
  __syncthreads();
  for(int pass=3; pass>=0; --pass){
    int shift = pass*8;
    hist[tid] = 0u;
    __syncthreads();
    unsigned prefix = s_prefix;
    unsigned mask = (pass==3) ? 0u : (0xFFFFFFFFu << ((pass+1)*8));
    for(int i=tid; i<Ll*Ll; i+=256){
      unsigned x = v[i];
      if((x & mask) == prefix) atomicAdd(&hist[(x >> shift) & 0xFF], 1u);
    }
    __syncthreads();
    if(tid == 0){
      int k = s_k, cum = 0;
      unsigned byte = 0;
      for(int bb=255; bb>=0; --bb){
        int c = (int)hist[bb];
        if(cum + c >= k){ byte = (unsigned)bb; s_k = k - cum; break; }
        cum += c;
      }
      s_prefix = prefix | (byte << shift);
    }
    __syncthreads();
  }
  if(tid == 0) kth[b] = __uint_as_float(s_prefix);
}

// ---------------- adjacency mask: diag | sel | sel^T ----------------
__global__ __launch_bounds__(256) void build_adj_kernel(
    const float* __restrict__ pattn, const float* __restrict__ kth,
    unsigned char* __restrict__ adj)
{
  int b = blockIdx.x >> 8, i = blockIdx.x & 255, j = threadIdx.x;
  float t = kth[b];
  const float* p = pattn + (size_t)b*Ll*Ll;
  bool e = (i==j) || (p[(size_t)i*Ll + j] >= t) || (p[(size_t)j*Ll + i] >= t);
  adj[(size_t)b*Ll*Ll + (size_t)i*Ll + j] = e ? 1 : 0;
}

// ---------------- repack Wh(layer,h,d,k) -> Wcat(layer, d, h*50+k) ----------------
__global__ void repack_wh_kernel(const float* __restrict__ Wh, float* __restrict__ wcat){
  int idx = blockIdx.x*blockDim.x + threadIdx.x;
  if(idx >= NLAYERS*Hh*MEMD*DKk) return;
  int layer = idx / (Hh*MEMD*DKk);
  int r = idx - layer*(Hh*MEMD*DKk);
  int h = r / (MEMD*DKk);
  int r2 = r - h*(MEMD*DKk);
  int d = r2 / DKk;
  int kk = r2 - d*DKk;
  wcat[(size_t)layer*MEMD*MEMD + (size_t)d*MEMD + h*DKk + kk] = Wh[idx];
}

// ---------------- s_i, s_j per (b,h,l) ----------------
__global__ void sisj_kernel(const float* __restrict__ proj, const float* __restrict__ awl,
                            float* __restrict__ si, float* __restrict__ sj)
{
  int idx = blockIdx.x*blockDim.x + threadIdx.x;
  if(idx >= Bb*Hh*Ll) return;
  int b = idx / (Hh*Ll);
  int r = idx - b*(Hh*Ll);
  int h = r / Ll;
  int l = r - h*Ll;
  const float* pr = proj + (((size_t)(b*Ll + l))*Hh + h)*DKk;
  const float* w1 = awl;
  const float* w2 = awl + DKk;
  float a = 0.f, c = 0.f;
  #pragma unroll
  for(int k2=0;k2<DKk;k2++){ float pv = pr[k2]; a = fmaf(pv, w1[k2], a); c = fmaf(pv, w2[k2], c); }
  si[idx] = a; sj[idx] = c;
}

// ---------------- fused GAT attention: per (b,h,l-half) block ----------------
// smem: projS[256*50] + sjS[256] + pS[256] + part[200] + red[8]  = 54080 B
__global__ __launch_bounds__(256) void gat_attn_kernel(
    const float* __restrict__ proj, const float* __restrict__ si, const float* __restrict__ sj,
    const unsigned char* __restrict__ adj, const float* __restrict__ abp,
    float* __restrict__ cat)
{
  extern __shared__ float sm[];
  float* projS = sm;                  // 12800
  float* sjS   = projS + Ll*DKk;      // 256
  float* pS    = sjS + Ll;            // 256
  float* part  = pS + Ll;             // 200
  float* red   = part + 200;          // 8

  int bh   = blockIdx.x >> 1;
  int half = blockIdx.x & 1;
  int b = bh / Hh, h = bh - b*Hh;
  int tid = threadIdx.x;

  for(int e=tid; e<Ll*DKk; e+=256){
    int m = e / DKk, kk = e - m*DKk;
    projS[e] = proj[(((size_t)(b*Ll + m))*Hh + h)*DKk + kk];
  }
  sjS[tid] = sj[(size_t)bh*Ll + tid];
  __syncthreads();

  float abv = abp[0];
  const unsigned char* adjb = adj + (size_t)b*Ll*Ll;

  int l0 = half * 128;
  for(int li=0; li<128; li++){
    int l = l0 + li;
    float si_l = si[(size_t)bh*Ll + l];
    int m = tid;
    float sval = si_l + sjS[m] + abv;
    sval = (sval > 0.f) ? sval : 0.2f*sval;
    bool ok = adjb[(size_t)l*Ll + m] != 0;
    float mx = blockMax256(ok ? sval : -3.0e38f, red);
    float e = ok ? expf(sval - mx) : 0.f;
    float s = blockSum256(e, red);
    pS[m] = e / s;
    __syncthreads();
    if(tid < 200){
      int k = tid % 50, c = tid / 50;
      float acc = 0.f;
      int mbase = c * 64;
      #pragma unroll 4
      for(int mm=0; mm<64; mm++)
        acc = fmaf(pS[mbase+mm], projS[(mbase+mm)*DKk + k], acc);
      part[c*50 + k] = acc;
    }
    __syncthreads();
    if(tid < 50){
      float o = part[tid] + part[50+tid] + part[100+tid] + part[150+tid];
      cat[((size_t)(b*Ll + l))*MEMD + h*DKk + tid] = o;
    }
    __syncthreads();
  }
}

// ---------------- res = h + cat; LayerNorm -> h (in place) ----------------
__global__ __launch_bounds__(256) void add_ln_kernel(
    float* __restrict__ hbuf, const float* __restrict__ cat,
    const float* __restrict__ g, const float* __restrict__ bln)
{
  __shared__ float rbuf[MEMD];
  __shared__ float red[8];
  int row = blockIdx.x, tid = threadIdx.x;
  float s = 0.f;
  for(int d=tid; d<MEMD; d+=256){
    float r = hbuf[(size_t)row*MEMD + d] + cat[(size_t)row*MEMD + d];
    rbuf[d] = r; s += r;
  }
  s = blockSum256(s, red);
  float mu = s * (1.f/MEMD);
  float v = 0.f;
  for(int d=tid; d<MEMD; d+=256){ float r = rbuf[d] - mu; v = fmaf(r, r, v); }
  v = blockSum256(v, red);
  float inv = 1.0f / sqrtf(v*(1.f/MEMD) + 1e-5f);
  for(int d=tid; d<MEMD; d+=256)
    hbuf[(size_t)row*MEMD + d] = (rbuf[d] - mu) * inv * g[d] + bln[d];
}

// ---------------- pooled = mean_l h; out = pooled @ Wc + bc ----------------
__global__ __launch_bounds__(256) void pool_classify_kernel(
    const float* __restrict__ hbuf, const float* __restrict__ Wc,
    const float* __restrict__ bc, float* __restrict__ out)
{
  __shared__ float pooled[MEMD];
  __shared__ float red[8];
  int b = blockIdx.x, tid = threadIdx.x;
  for(int d=tid; d<MEMD; d+=256){
    float s = 0.f;
    for(int l=0; l<Ll; l++) s += hbuf[((size_t)(b*Ll + l))*MEMD + d];
    pooled[d] = s * (1.f/Ll);
  }
  __syncthreads();
  for(int c=0; c<NCc; c++){
    float p = 0.f;
    for(int d=tid; d<MEMD; d+=256) p = fmaf(pooled[d], Wc[d*NCc + c], p);
    p = blockSum256(p, red);
    if(tid == 0) out[b*NCc + c] = p + bc[c];
  }
}

// ---------------- launcher ----------------
extern "C" void kernel_launch(void* const* d_in, const int* in_sizes, int n_in,
                              void* d_out, int out_size)
{
  const float* x    = (const float*)d_in[0];
  const float* wq   = (const float*)d_in[1];
  const float* bq   = (const float*)d_in[2];
  const float* wk   = (const float*)d_in[3];
  const float* bk   = (const float*)d_in[4];
  const float* w_in = (const float*)d_in[5];
  const float* b_in = (const float*)d_in[6];
  const float* Wh   = (const float*)d_in[7];
  const float* bh   = (const float*)d_in[8];
  const float* aw   = (const float*)d_in[9];
  const float* ab   = (const float*)d_in[10];
  const float* g_ln = (const float*)d_in[11];
  const float* b_ln = (const float*)d_in[12];
  const float* Wc   = (const float*)d_in[13];
  const float* bc   = (const float*)d_in[14];
  float* out = (float*)d_out;

  float *pq, *pk, *pscores, *ppattn, *pkth, *ph, *pproj, *pcat, *psi, *psj, *pwcat;
  unsigned char* padj;
  cudaGetSymbolAddress((void**)&pq, g_q);
  cudaGetSymbolAddress((void**)&pk, g_k);
  cudaGetSymbolAddress((void**)&pscores, g_scores);
  cudaGetSymbolAddress((void**)&ppattn, g_pattn);
  cudaGetSymbolAddress((void**)&pkth, g_kth);
  cudaGetSymbolAddress((void**)&padj, g_adj);
  cudaGetSymbolAddress((void**)&ph, g_h);
  cudaGetSymbolAddress((void**)&pproj, g_proj);
  cudaGetSymbolAddress((void**)&pcat, g_cat);
  cudaGetSymbolAddress((void**)&psi, g_si);
  cudaGetSymbolAddress((void**)&psj, g_sj);
  cudaGetSymbolAddress((void**)&pwcat, g_wcat);

  const int ATTN_SMEM = (Ll*DKk + Ll + Ll + 200 + 8) * 4; // 54080 bytes
  cudaFuncSetAttribute(gat_attn_kernel, cudaFuncAttributeMaxDynamicSharedMemorySize, ATTN_SMEM);

  // q, k projections
  sgemm128<<<dim3(DIN/128, BL/128), 256>>>(x, wq, bq, pq, BL, DIN, DIN);
  sgemm128<<<dim3(DIN/128, BL/128), 256>>>(x, wk, bk, pk, BL, DIN, DIN);

  // scores + softmax + head-mean
  qk_scores_kernel<<<dim3(16, Bb*Hh), 256>>>(pq, pk, pscores);
  softmax_mean_kernel<<<Bb*Ll, 256>>>(pscores, ppattn);

  // top-k threshold + adjacency
  topk_select_kernel<<<Bb, 256>>>(ppattn, pkth);
  build_adj_kernel<<<Bb*Ll, 256>>>(ppattn, pkth, padj);

  // h = x @ w_in + b_in
  sgemm128<<<dim3((MEMD+127)/128, BL/128), 256>>>(x, w_in, b_in, ph, BL, MEMD, DIN);

  // repack Wh into (layer, MEM, H*DK)
  repack_wh_kernel<<<(NLAYERS*Hh*MEMD*DKk + 255)/256, 256>>>(Wh, pwcat);

  for(int layer=0; layer<NLAYERS; layer++){
    // proj (B,L,H,DK) = h @ Wcat[layer] + bh[layer]
    sgemm128<<<dim3((MEMD+127)/128, BL/128), 256>>>(
        ph, pwcat + (size_t)layer*MEMD*MEMD, bh + layer*MEMD, pproj, BL, MEMD, MEMD);
    sisj_kernel<<<(Bb*Hh*Ll + 127)/128, 128>>>(pproj, aw + layer*2*DKk, psi, psj);
    gat_attn_kernel<<<Bb*Hh*2, 256, ATTN_SMEM>>>(pproj, psi, psj, padj, ab + layer, pcat);
    add_ln_kernel<<<Bb*Ll, 256>>>(ph, pcat, g_ln + layer*MEMD, b_ln + layer*MEMD);
  }

  pool_classify_kernel<<<Bb, 256>>>(ph, Wc, bc, out);
}

// round 2
// speedup vs baseline: 1.1369x; 1.1369x over previous
#include <cuda_runtime.h>
#include <math.h>

#define Bb 64
#define Ll 256
#define DIN 768
#define MEMD 300
#define Hh 6
#define TOPK 1024
#define NCc 3
#define NLAYERS 2
#define DKk 50
#define BL (Bb*Ll)   // 16384

// ---------------- scratch (device globals; no runtime allocation) ----------------
__device__ float g_q[BL*DIN];                 // 50 MB
__device__ float g_k[BL*DIN];                 // 50 MB
__device__ float g_scores[Bb*Hh*Ll*Ll];       // 100 MB
__device__ float g_pattn[Bb*Ll*Ll];           // 16.8 MB
__device__ float g_kth[Bb];
__device__ unsigned char g_adj[Bb*Ll*Ll];     // 4.2 MB
__device__ float g_h[BL*MEMD];                // 19.7 MB
__device__ float g_proj[BL*MEMD];             // 19.7 MB
__device__ float g_cat[BL*MEMD];              // 19.7 MB
__device__ float g_si[Bb*Hh*Ll];
__device__ float g_sj[Bb*Hh*Ll];
__device__ float g_wcat[NLAYERS*MEMD*MEMD];   // repacked Wh

// ---------------- packed fp32x2 FMA helpers (Blackwell) ----------------
#define FFMA2(acc, a2, b2) \
  asm("fma.rn.f32x2 %0, %1, %2, %3;" : "=l"(acc) : "l"(a2), "l"(b2), "l"(acc))

__device__ __forceinline__ unsigned long long dup_f32(float x){
  unsigned long long r;
  asm("mov.b64 %0, {%1, %1};" : "=l"(r) : "f"(x));
  return r;
}
__device__ __forceinline__ float2 unpack2(unsigned long long v){
  float2 c;
  asm("mov.b64 {%0, %1}, %2;" : "=f"(c.x), "=f"(c.y) : "l"(v));
  return c;
}

// ---------------- reduction helpers (256 threads) ----------------
__device__ __forceinline__ float warpSum(float v){
  #pragma unroll
  for(int o=16;o;o>>=1) v += __shfl_xor_sync(0xffffffffu, v, o);
  return v;
}
__device__ __forceinline__ float warpMax(float v){
  #pragma unroll
  for(int o=16;o;o>>=1) v = fmaxf(v, __shfl_xor_sync(0xffffffffu, v, o));
  return v;
}
__device__ __forceinline__ float blockSum256(float v, float* sh){
  v = warpSum(v);
  int w = threadIdx.x >> 5;
  if((threadIdx.x & 31) == 0) sh[w] = v;
  __syncthreads();
  if(threadIdx.x < 8){
    float x = sh[threadIdx.x];
    #pragma unroll
    for(int o=4;o;o>>=1) x += __shfl_xor_sync(0xffu, x, o);
    if(threadIdx.x==0) sh[0] = x;
  }
  __syncthreads();
  float r = sh[0];
  __syncthreads();
  return r;
}
__device__ __forceinline__ float blockMax256(float v, float* sh){
  v = warpMax(v);
  int w = threadIdx.x >> 5;
  if((threadIdx.x & 31) == 0) sh[w] = v;
  __syncthreads();
  if(threadIdx.x < 8){
    float x = sh[threadIdx.x];
    #pragma unroll
    for(int o=4;o;o>>=1) x = fmaxf(x, __shfl_xor_sync(0xffu, x, o));
    if(threadIdx.x==0) sh[0] = x;
  }
  __syncthreads();
  float r = sh[0];
  __syncthreads();
  return r;
}

// =====================================================================
// SGEMM (double-buffered, BK=16, FFMA2): C[M,N] = A[M,K] @ W[K,N] + bias
// 128x128 tile, 256 threads, 8x8 microtile. M % 128 == 0. K,N % 4 == 0.
// =====================================================================
__global__ __launch_bounds__(256) void sgemm128db(
    const float* __restrict__ A, const float* __restrict__ W,
    const float* __restrict__ bias, float* __restrict__ C,
    int M, int N, int K)
{
  __shared__ __align__(16) float As[2][16][128];
  __shared__ __align__(16) float Ws[2][16][128];
  int tid = threadIdx.x;
  int tx = tid & 15, ty = tid >> 4;
  int row0 = blockIdx.y * 128, col0 = blockIdx.x * 128;
  int nStages = (K + 15) >> 4;

  unsigned long long acc2[8][4];
  #pragma unroll
  for(int i=0;i<8;i++)
    #pragma unroll
    for(int j=0;j<4;j++) acc2[i][j] = 0ull;

  // per-thread load coords
  // A: f = tid + i*256, row=f>>2, kq=f&3  -> A[row0+row][k0+kq*4 .. +3]
  // W: f = tid + i*256, kk=f>>5, nq=f&31  -> W[k0+kk][col0+nq*4 .. +3]
  float4 pa[2], pw[2];

  // ---- stage 0 load ----
  {
    int k0 = 0;
    #pragma unroll
    for(int i=0;i<2;i++){
      int f = tid + i*256; int row = f>>2, kq = f&3;
      int gk = k0 + kq*4;
      pa[i] = (gk < K) ? *(const float4*)&A[(size_t)(row0+row)*K + gk]
                       : make_float4(0.f,0.f,0.f,0.f);
    }
    #pragma unroll
    for(int i=0;i<2;i++){
      int f = tid + i*256; int kk = f>>5, nq = f&31;
      int gk = k0 + kk, gc = col0 + nq*4;
      pw[i] = (gk < K && gc < N) ? *(const float4*)&W[(size_t)gk*N + gc]
                                 : make_float4(0.f,0.f,0.f,0.f);
    }
    #pragma unroll
    for(int i=0;i<2;i++){
      int f = tid + i*256; int row = f>>2, kq = f&3;
      As[0][kq*4+0][row] = pa[i].x; As[0][kq*4+1][row] = pa[i].y;
      As[0][kq*4+2][row] = pa[i].z; As[0][kq*4+3][row] = pa[i].w;
    }
    #pragma unroll
    for(int i=0;i<2;i++){
      int f = tid + i*256; int kk = f>>5, nq = f&31;
      *(float4*)&Ws[0][kk][nq*4] = pw[i];
    }
  }
  __syncthreads();

  for(int s=0; s<nStages; s++){
    int p = s & 1;
    if(s+1 < nStages){
      int k0 = (s+1)*16;
      #pragma unroll
      for(int i=0;i<2;i++){
        int f = tid + i*256; int row = f>>2, kq = f&3;
        int gk = k0 + kq*4;
        pa[i] = (gk < K) ? *(const float4*)&A[(size_t)(row0+row)*K + gk]
                         : make_float4(0.f,0.f,0.f,0.f);
      }
      #pragma unroll
      for(int i=0;i<2;i++){
        int f = tid + i*256; int kk = f>>5, nq = f&31;
        int gk = k0 + kk, gc = col0 + nq*4;
        pw[i] = (gk < K && gc < N) ? *(const float4*)&W[(size_t)gk*N + gc]
                                   : make_float4(0.f,0.f,0.f,0.f);
      }
    }
    #pragma unroll
    for(int kk=0;kk<16;kk++){
      float a[8];
      *(float4*)(a)   = *(const float4*)&As[p][kk][ty*8];
      *(float4*)(a+4) = *(const float4*)&As[p][kk][ty*8+4];
      unsigned long long bp[4];
      const unsigned long long* wp = (const unsigned long long*)&Ws[p][kk][tx*8];
      bp[0]=wp[0]; bp[1]=wp[1]; bp[2]=wp[2]; bp[3]=wp[3];
      #pragma unroll
      for(int i=0;i<8;i++){
        unsigned long long ad = dup_f32(a[i]);
        #pragma unroll
        for(int j=0;j<4;j++) FFMA2(acc2[i][j], ad, bp[j]);
      }
    }
    if(s+1 < nStages){
      int q = (s+1)&1;
      #pragma unroll
      for(int i=0;i<2;i++){
        int f = tid + i*256; int row = f>>2, kq = f&3;
        As[q][kq*4+0][row] = pa[i].x; As[q][kq*4+1][row] = pa[i].y;
        As[q][kq*4+2][row] = pa[i].z; As[q][kq*4+3][row] = pa[i].w;
      }
      #pragma unroll
      for(int i=0;i<2;i++){
        int f = tid + i*256; int kk = f>>5, nq = f&31;
        *(float4*)&Ws[q][kk][nq*4] = pw[i];
      }
      __syncthreads();
    }
  }

  #pragma unroll
  for(int i=0;i<8;i++){
    int gr = row0 + ty*8 + i;
    #pragma unroll
    for(int j=0;j<4;j++){
      int gc = col0 + tx*8 + 2*j;
      if(gc < N){
        float2 c = unpack2(acc2[i][j]);
        C[(size_t)gr*N + gc]     = c.x + bias[gc];
        C[(size_t)gr*N + gc + 1] = c.y + bias[gc+1];
      }
    }
  }
}

// =====================================================================
// QK^T scores (NT GEMM, strided, K=128 fixed, FFMA2), fused 1/sqrt(128)
// per (b,h): scores[l,m] = q_h[l,:].k_h[m,:] * scale ; 128x128 tiles
// =====================================================================
__global__ __launch_bounds__(256) void qk_scores128(
    const float* __restrict__ q, const float* __restrict__ k,
    float* __restrict__ scores)
{
  __shared__ __align__(16) float As[2][16][128];
  __shared__ __align__(16) float Bs[2][16][128];
  int bh = blockIdx.z;
  int b = bh / Hh, h = bh - b*Hh;
  const float* Ab = q + (size_t)b*Ll*DIN + (size_t)h*128;
  const float* Bb2 = k + (size_t)b*Ll*DIN + (size_t)h*128;
  int tid = threadIdx.x;
  int tx = tid & 15, ty = tid >> 4;
  int row0 = blockIdx.y * 128, col0 = blockIdx.x * 128;
  const int nStages = 8; // K=128

  unsigned long long acc2[8][4];
  #pragma unroll
  for(int i=0;i<8;i++)
    #pragma unroll
    for(int j=0;j<4;j++) acc2[i][j] = 0ull;

  float4 pa[2], pb[2];
  {
    #pragma unroll
    for(int i=0;i<2;i++){
      int f = tid + i*256; int row = f>>2, kq = f&3;
      pa[i] = *(const float4*)&Ab[(size_t)(row0+row)*DIN + kq*4];
      pb[i] = *(const float4*)&Bb2[(size_t)(col0+row)*DIN + kq*4];
    }
    #pragma unroll
    for(int i=0;i<2;i++){
      int f = tid + i*256; int row = f>>2, kq = f&3;
      As[0][kq*4+0][row]=pa[i].x; As[0][kq*4+1][row]=pa[i].y;
      As[0][kq*4+2][row]=pa[i].z; As[0][kq*4+3][row]=pa[i].w;
      Bs[0][kq*4+0][row]=pb[i].x; Bs[0][kq*4+1][row]=pb[i].y;
      Bs[0][kq*4+2][row]=pb[i].z; Bs[0][kq*4+3][row]=pb[i].w;
    }
  }
  __syncthreads();

  for(int s=0; s<nStages; s++){
    int p = s & 1;
    if(s+1 < nStages){
      int k0 = (s+1)*16;
      #pragma unroll
      for(int i=0;i<2;i++){
        int f = tid + i*256; int row = f>>2, kq = f&3;
        pa[i] = *(const float4*)&Ab[(size_t)(row0+row)*DIN + k0 + kq*4];
        pb[i] = *(const float4*)&Bb2[(size_t)(col0+row)*DIN + k0 + kq*4];
      }
    }
    #pragma unroll
    for(int kk=0;kk<16;kk++){
      float a[8];
      *(float4*)(a)   = *(const float4*)&As[p][kk][ty*8];
      *(float4*)(a+4) = *(const float4*)&As[p][kk][ty*8+4];
      unsigned long long bp[4];
      const unsigned long long* wp = (const unsigned long long*)&Bs[p][kk][tx*8];
      bp[0]=wp[0]; bp[1]=wp[1]; bp[2]=wp[2]; bp[3]=wp[3];
      #pragma unroll
      for(int i=0;i<8;i++){
        unsigned long long ad = dup_f32(a[i]);
        #pragma unroll
        for(int j=0;j<4;j++) FFMA2(acc2[i][j], ad, bp[j]);
      }
    }
    if(s+1 < nStages){
      int qb = (s+1)&1;
      #pragma unroll
      for(int i=0;i<2;i++){
        int f = tid + i*256; int row = f>>2, kq = f&3;
        As[qb][kq*4+0][row]=pa[i].x; As[qb][kq*4+1][row]=pa[i].y;
        As[qb][kq*4+2][row]=pa[i].z; As[qb][kq*4+3][row]=pa[i].w;
        Bs[qb][kq*4+0][row]=pb[i].x; Bs[qb][kq*4+1][row]=pb[i].y;
        Bs[qb][kq*4+2][row]=pb[i].z; Bs[qb][kq*4+3][row]=pb[i].w;
      }
      __syncthreads();
    }
  }

  const float scale = 0.08838834764831845f; // 1/sqrt(128)
  #pragma unroll
  for(int i=0;i<8;i++){
    int gl = row0 + ty*8 + i;
    #pragma unroll
    for(int j=0;j<4;j++){
      int gm = col0 + tx*8 + 2*j;
      float2 c = unpack2(acc2[i][j]);
      float* dst = &scores[((size_t)bh*Ll + gl)*Ll + gm];
      dst[0] = c.x * scale;
      dst[1] = c.y * scale;
    }
  }
}

// ---------------- softmax over m per (b,l), all 6 heads batched ----------------
__global__ __launch_bounds__(256) void softmax_mean_kernel(
    const float* __restrict__ scores, float* __restrict__ pattn)
{
  __shared__ float red1[Hh][8];
  __shared__ float r1[Hh];
  __shared__ float red2[Hh][8];
  __shared__ float r2[Hh];
  int bl = blockIdx.x;
  int b = bl >> 8, l = bl & 255;
  int m = threadIdx.x, w = m >> 5, lane = m & 31;
  const float* base = scores + ((size_t)(b*Hh)*Ll + l)*Ll + m;
  float s[Hh];
  #pragma unroll
  for(int h=0;h<Hh;h++) s[h] = base[(size_t)h*Ll*Ll];

  float v[Hh];
  #pragma unroll
  for(int h=0;h<Hh;h++){
    v[h] = s[h];
    #pragma unroll
    for(int o=16;o;o>>=1) v[h] = fmaxf(v[h], __shfl_xor_sync(0xffffffffu, v[h], o));
  }
  if(lane == 0){
    #pragma unroll
    for(int h=0;h<Hh;h++) red1[h][w] = v[h];
  }
  __syncthreads();
  if(m < Hh){
    float x = red1[m][0];
    #pragma unroll
    for(int j=1;j<8;j++) x = fmaxf(x, red1[m][j]);
    r1[m] = x;
  }
  __syncthreads();

  float e[Hh];
  #pragma unroll
  for(int h=0;h<Hh;h++){
    e[h] = expf(s[h] - r1[h]);
    v[h] = e[h];
    #pragma unroll
    for(int o=16;o;o>>=1) v[h] += __shfl_xor_sync(0xffffffffu, v[h], o);
  }
  if(lane == 0){
    #pragma unroll
    for(int h=0;h<Hh;h++) red2[h][w] = v[h];
  }
  __syncthreads();
  if(m < Hh){
    float x = red2[m][0];
    #pragma unroll
    for(int j=1;j<8;j++) x += red2[m][j];
    r2[m] = x;
  }
  __syncthreads();

  float acc = 0.f;
  #pragma unroll
  for(int h=0;h<Hh;h++) acc += e[h] / r2[h];
  pattn[(size_t)bl*Ll + m] = acc * (1.f/6.f);
}

// ---------------- exact 1024th-largest per batch via radix select ----------------
__global__ __launch_bounds__(1024) void topk_select_kernel(
    const float* __restrict__ pattn, float* __restrict__ kth)
{
  int b = blockIdx.x;
  int tid = threadIdx.x;
  const unsigned* v = (const unsigned*)(pattn + (size_t)b*Ll*Ll);
  __shared__ unsigned hist[256];
  __shared__ unsigned s_prefix;
  __shared__ int s_k;
  if(tid == 0){ s_prefix = 0u; s_k = TOPK; }
  __syncthreads();
  for(int pass=3; pass>=0; --pass){
    int shift = pass*8;
    if(tid < 256) hist[tid] = 0u;
    __syncthreads();
    unsigned prefix = s_prefix;
    unsigned mask = (pass==3) ? 0u : (0xFFFFFFFFu << ((pass+1)*8));
    for(int i=tid; i<Ll*Ll; i+=1024){
      unsigned x = v[i];
      if((x & mask) == prefix) atomicAdd(&hist[(x >> shift) & 0xFF], 1u);
    }
    __syncthreads();
    if(tid == 0){
      int k = s_k, cum = 0;
      unsigned byte = 0;
      for(int bb=255; bb>=0; --bb){
        int c = (int)hist[bb];
        if(cum + c >= k){ byte = (unsigned)bb; s_k = k - cum; break; }
        cum += c;
      }
      s_prefix = prefix | (byte << shift);
    }
    __syncthreads();
  }
  if(tid == 0) kth[b] = __uint_as_float(s_prefix);
}

// ---------------- adjacency mask: diag | sel | sel^T ----------------
__global__ __launch_bounds__(256) void build_adj_kernel(
    const float* __restrict__ pattn, const float* __restrict__ kth,
    unsigned char* __restrict__ adj)
{
  int b = blockIdx.x >> 8, i = blockIdx.x & 255, j = threadIdx.x;
  float t = kth[b];
  const float* p = pattn + (size_t)b*Ll*Ll;
  bool e = (i==j) || (p[(size_t)i*Ll + j] >= t) || (p[(size_t)j*Ll + i] >= t);
  adj[(size_t)b*Ll*Ll + (size_t)i*Ll + j] = e ? 1 : 0;
}

// ---------------- repack Wh(layer,h,d,k) -> Wcat(layer, d, h*50+k) ----------------
__global__ void repack_wh_kernel(const float* __restrict__ Wh, float* __restrict__ wcat){
  int idx = blockIdx.x*blockDim.x + threadIdx.x;
  if(idx >= NLAYERS*Hh*MEMD*DKk) return;
  int layer = idx / (Hh*MEMD*DKk);
  int r = idx - layer*(Hh*MEMD*DKk);
  int h = r / (MEMD*DKk);
  int r2 = r - h*(MEMD*DKk);
  int d = r2 / DKk;
  int kk = r2 - d*DKk;
  wcat[(size_t)layer*MEMD*MEMD + (size_t)d*MEMD + h*DKk + kk] = Wh[idx];
}

// ---------------- s_i, s_j per (b,h,l) ----------------
__global__ void sisj_kernel(const float* __restrict__ proj, const float* __restrict__ awl,
                            float* __restrict__ si, float* __restrict__ sj)
{
  int idx = blockIdx.x*blockDim.x + threadIdx.x;
  if(idx >= Bb*Hh*Ll) return;
  int b = idx / (Hh*Ll);
  int r = idx - b*(Hh*Ll);
  int h = r / Ll;
  int l = r - h*Ll;
  const float* pr = proj + (((size_t)(b*Ll + l))*Hh + h)*DKk;
  const float* w1 = awl;
  const float* w2 = awl + DKk;
  float a = 0.f, c = 0.f;
  #pragma unroll
  for(int k2=0;k2<DKk;k2++){ float pv = pr[k2]; a = fmaf(pv, w1[k2], a); c = fmaf(pv, w2[k2], c); }
  si[idx] = a; sj[idx] = c;
}

// ---------------- fused GAT attention: per (b,h,l-half) block ----------------
__global__ __launch_bounds__(256) void gat_attn_kernel(
    const float* __restrict__ proj, const float* __restrict__ si, const float* __restrict__ sj,
    const unsigned char* __restrict__ adj, const float* __restrict__ abp,
    float* __restrict__ cat)
{
  extern __shared__ float sm[];
  float* projS = sm;                  // 256*50
  float* sjS   = projS + Ll*DKk;      // 256
  float* pS    = sjS + Ll;            // 256
  float* part  = pS + Ll;             // 200
  float* red   = part + 200;          // 8

  int bh   = blockIdx.x >> 1;
  int half = blockIdx.x & 1;
  int b = bh / Hh, h = bh - b*Hh;
  int tid = threadIdx.x;

  for(int e=tid; e<Ll*DKk; e+=256){
    int m = e / DKk, kk = e - m*DKk;
    projS[e] = proj[(((size_t)(b*Ll + m))*Hh + h)*DKk + kk];
  }
  sjS[tid] = sj[(size_t)bh*Ll + tid];
  __syncthreads();

  float abv = abp[0];
  const unsigned char* adjb = adj + (size_t)b*Ll*Ll;

  int l0 = half * 128;
  for(int li=0; li<128; li++){
    int l = l0 + li;
    float si_l = si[(size_t)bh*Ll + l];
    int m = tid;
    float sval = si_l + sjS[m] + abv;
    sval = (sval > 0.f) ? sval : 0.2f*sval;
    bool ok = adjb[(size_t)l*Ll + m] != 0;
    float mx = blockMax256(ok ? sval : -3.0e38f, red);
    float e = ok ? expf(sval - mx) : 0.f;
    float s = blockSum256(e, red);
    pS[m] = e / s;
    __syncthreads();
    if(tid < 200){
      int k = tid % 50, c = tid / 50;
      float acc = 0.f;
      int mbase = c * 64;
      #pragma unroll 4
      for(int mm=0; mm<64; mm++)
        acc = fmaf(pS[mbase+mm], projS[(mbase+mm)*DKk + k], acc);
      part[c*50 + k] = acc;
    }
    __syncthreads();
    if(tid < 50){
      float o = part[tid] + part[50+tid] + part[100+tid] + part[150+tid];
      cat[((size_t)(b*Ll + l))*MEMD + h*DKk + tid] = o;
    }
    __syncthreads();
  }
}

// ---------------- res = h + cat; LayerNorm -> h (in place) ----------------
__global__ __launch_bounds__(256) void add_ln_kernel(
    float* __restrict__ hbuf, const float* __restrict__ cat,
    const float* __restrict__ g, const float* __restrict__ bln)
{
  __shared__ float rbuf[MEMD];
  __shared__ float red[8];
  int row = blockIdx.x, tid = threadIdx.x;
  float s = 0.f;
  for(int d=tid; d<MEMD; d+=256){
    float r = hbuf[(size_t)row*MEMD + d] + cat[(size_t)row*MEMD + d];
    rbuf[d] = r; s += r;
  }
  s = blockSum256(s, red);
  float mu = s * (1.f/MEMD);
  float v = 0.f;
  for(int d=tid; d<MEMD; d+=256){ float r = rbuf[d] - mu; v = fmaf(r, r, v); }
  v = blockSum256(v, red);
  float inv = 1.0f / sqrtf(v*(1.f/MEMD) + 1e-5f);
  for(int d=tid; d<MEMD; d+=256)
    hbuf[(size_t)row*MEMD + d] = (rbuf[d] - mu) * inv * g[d] + bln[d];
}

// ---------------- pooled = mean_l h; out = pooled @ Wc + bc ----------------
__global__ __launch_bounds__(256) void pool_classify_kernel(
    const float* __restrict__ hbuf, const float* __restrict__ Wc,
    const float* __restrict__ bc, float* __restrict__ out)
{
  __shared__ float pooled[MEMD];
  __shared__ float red[8];
  int b = blockIdx.x, tid = threadIdx.x;
  for(int d=tid; d<MEMD; d+=256){
    float s = 0.f;
    for(int l=0; l<Ll; l++) s += hbuf[((size_t)(b*Ll + l))*MEMD + d];
    pooled[d] = s * (1.f/Ll);
  }
  __syncthreads();
  for(int c=0; c<NCc; c++){
    float p = 0.f;
    for(int d=tid; d<MEMD; d+=256) p = fmaf(pooled[d], Wc[d*NCc + c], p);
    p = blockSum256(p, red);
    if(tid == 0) out[b*NCc + c] = p + bc[c];
  }
}

// ---------------- launcher ----------------
extern "C" void kernel_launch(void* const* d_in, const int* in_sizes, int n_in,
                              void* d_out, int out_size)
{
  const float* x    = (const float*)d_in[0];
  const float* wq   = (const float*)d_in[1];
  const float* bq   = (const float*)d_in[2];
  const float* wk   = (const float*)d_in[3];
  const float* bk   = (const float*)d_in[4];
  const float* w_in = (const float*)d_in[5];
  const float* b_in = (const float*)d_in[6];
  const float* Wh   = (const float*)d_in[7];
  const float* bh   = (const float*)d_in[8];
  const float* aw   = (const float*)d_in[9];
  const float* ab   = (const float*)d_in[10];
  const float* g_ln = (const float*)d_in[11];
  const float* b_ln = (const float*)d_in[12];
  const float* Wc   = (const float*)d_in[13];
  const float* bc   = (const float*)d_in[14];
  float* out = (float*)d_out;

  float *pq, *pk, *pscores, *ppattn, *pkth, *ph, *pproj, *pcat, *psi, *psj, *pwcat;
  unsigned char* padj;
  cudaGetSymbolAddress((void**)&pq, g_q);
  cudaGetSymbolAddress((void**)&pk, g_k);
  cudaGetSymbolAddress((void**)&pscores, g_scores);
  cudaGetSymbolAddress((void**)&ppattn, g_pattn);
  cudaGetSymbolAddress((void**)&pkth, g_kth);
  cudaGetSymbolAddress((void**)&padj, g_adj);
  cudaGetSymbolAddress((void**)&ph, g_h);
  cudaGetSymbolAddress((void**)&pproj, g_proj);
  cudaGetSymbolAddress((void**)&pcat, g_cat);
  cudaGetSymbolAddress((void**)&psi, g_si);
  cudaGetSymbolAddress((void**)&psj, g_sj);
  cudaGetSymbolAddress((void**)&pwcat, g_wcat);

  const int ATTN_SMEM = (Ll*DKk + Ll + Ll + 200 + 8) * 4; // 54080 bytes
  cudaFuncSetAttribute(gat_attn_kernel, cudaFuncAttributeMaxDynamicSharedMemorySize, ATTN_SMEM);

  // q, k projections
  sgemm128db<<<dim3(DIN/128, BL/128), 256>>>(x, wq, bq, pq, BL, DIN, DIN);
  sgemm128db<<<dim3(DIN/128, BL/128), 256>>>(x, wk, bk, pk, BL, DIN, DIN);

  // scores + softmax + head-mean
  qk_scores128<<<dim3(2, 2, Bb*Hh), 256>>>(pq, pk, pscores);
  softmax_mean_kernel<<<Bb*Ll, 256>>>(pscores, ppattn);

  // top-k threshold + adjacency
  topk_select_kernel<<<Bb, 1024>>>(ppattn, pkth);
  build_adj_kernel<<<Bb*Ll, 256>>>(ppattn, pkth, padj);

  // h = x @ w_in + b_in
  sgemm128db<<<dim3((MEMD+127)/128, BL/128), 256>>>(x, w_in, b_in, ph, BL, MEMD, DIN);

  // repack Wh into (layer, MEM, H*DK)
  repack_wh_kernel<<<(NLAYERS*Hh*MEMD*DKk + 255)/256, 256>>>(Wh, pwcat);

  for(int layer=0; layer<NLAYERS; layer++){
    sgemm128db<<<dim3((MEMD+127)/128, BL/128), 256>>>(
        ph, pwcat + (size_t)layer*MEMD*MEMD, bh + layer*MEMD, pproj, BL, MEMD, MEMD);
    sisj_kernel<<<(Bb*Hh*Ll + 127)/128, 128>>>(pproj, aw + layer*2*DKk, psi, psj);
    gat_attn_kernel<<<Bb*Hh*2, 256, ATTN_SMEM>>>(pproj, psi, psj, padj, ab + layer, pcat);
    add_ln_kernel<<<Bb*Ll, 256>>>(ph, pcat, g_ln + layer*MEMD, b_ln + layer*MEMD);
  }

  pool_classify_kernel<<<Bb, 256>>>(ph, Wc, bc, out);
}

// round 4
// speedup vs baseline: 1.9506x; 1.7157x over previous
#include <cuda_runtime.h>
#include <math.h>

#define Bb 64
#define Ll 256
#define DIN 768
#define MEMD 300
#define Hh 6
#define TOPK 1024
#define NCc 3
#define NLAYERS 2
#define DKk 50
#define BL (Bb*Ll)   // 16384

// ---------------- scratch (device globals; no runtime allocation) ----------------
__device__ float g_q[BL*DIN];                 // 50 MB
__device__ float g_k[BL*DIN];                 // 50 MB
__device__ float g_scores[Bb*Hh*Ll*Ll];       // 100 MB
__device__ float g_pattn[Bb*Ll*Ll];           // 16.8 MB
__device__ float g_kth[Bb];
__device__ unsigned char g_adj[Bb*Ll*Ll];     // 4.2 MB
__device__ float g_h[BL*MEMD];                // 19.7 MB
__device__ float g_proj[BL*MEMD];             // 19.7 MB
__device__ float g_cat[BL*MEMD];              // 19.7 MB
__device__ float g_si[Bb*Hh*Ll];
__device__ float g_sj[Bb*Hh*Ll];
__device__ float g_wcat[NLAYERS*MEMD*MEMD];   // repacked Wh

// ---------------- packed fp32x2 FMA helpers (Blackwell) ----------------
#define FFMA2(acc, a2, b2) \
  asm("fma.rn.f32x2 %0, %1, %2, %3;" : "=l"(acc) : "l"(a2), "l"(b2), "l"(acc))

__device__ __forceinline__ unsigned long long dup_f32(float x){
  unsigned long long r;
  asm("mov.b64 %0, {%1, %1};" : "=l"(r) : "f"(x));
  return r;
}
__device__ __forceinline__ float2 unpack2(unsigned long long v){
  float2 c;
  asm("mov.b64 {%0, %1}, %2;" : "=f"(c.x), "=f"(c.y) : "l"(v));
  return c;
}

// ---------------- reduction helpers ----------------
__device__ __forceinline__ float warpSum(float v){
  #pragma unroll
  for(int o=16;o;o>>=1) v += __shfl_xor_sync(0xffffffffu, v, o);
  return v;
}
__device__ __forceinline__ float blockSum256(float v, float* sh){
  v = warpSum(v);
  int w = threadIdx.x >> 5;
  if((threadIdx.x & 31) == 0) sh[w] = v;
  __syncthreads();
  if(threadIdx.x < 8){
    float x = sh[threadIdx.x];
    #pragma unroll
    for(int o=4;o;o>>=1) x += __shfl_xor_sync(0xffu, x, o);
    if(threadIdx.x==0) sh[0] = x;
  }
  __syncthreads();
  float r = sh[0];
  __syncthreads();
  return r;
}

// =====================================================================
// SGEMM (double-buffered, BK=16, FFMA2, 4+4 split fragments)
// C[M,N] = A[M,K] @ W[K,N] + bias ; 128x128 tile, 256 threads, 8x8 micro
// =====================================================================
__global__ __launch_bounds__(256) void sgemm128db(
    const float* __restrict__ A, const float* __restrict__ W,
    const float* __restrict__ bias, float* __restrict__ C,
    int M, int N, int K)
{
  __shared__ __align__(16) float As[2][16][128];
  __shared__ __align__(16) float Ws[2][16][128];
  int tid = threadIdx.x;
  int tx = tid & 15, ty = tid >> 4;
  int row0 = blockIdx.y * 128, col0 = blockIdx.x * 128;
  int nStages = (K + 15) >> 4;

  unsigned long long acc2[8][4];
  #pragma unroll
  for(int i=0;i<8;i++)
    #pragma unroll
    for(int j=0;j<4;j++) acc2[i][j] = 0ull;

  float4 pa[2], pw[2];

  // ---- stage 0 load ----
  {
    #pragma unroll
    for(int i=0;i<2;i++){
      int f = tid + i*256; int row = f>>2, kq = f&3;
      int gk = kq*4;
      pa[i] = (gk < K) ? *(const float4*)&A[(size_t)(row0+row)*K + gk]
                       : make_float4(0.f,0.f,0.f,0.f);
    }
    #pragma unroll
    for(int i=0;i<2;i++){
      int f = tid + i*256; int kk = f>>5, nq = f&31;
      int gk = kk, gc = col0 + nq*4;
      pw[i] = (gk < K && gc < N) ? *(const float4*)&W[(size_t)gk*N + gc]
                                 : make_float4(0.f,0.f,0.f,0.f);
    }
    #pragma unroll
    for(int i=0;i<2;i++){
      int f = tid + i*256; int row = f>>2, kq = f&3;
      As[0][kq*4+0][row] = pa[i].x; As[0][kq*4+1][row] = pa[i].y;
      As[0][kq*4+2][row] = pa[i].z; As[0][kq*4+3][row] = pa[i].w;
    }
    #pragma unroll
    for(int i=0;i<2;i++){
      int f = tid + i*256; int kk = f>>5, nq = f&31;
      *(float4*)&Ws[0][kk][nq*4] = pw[i];
    }
  }
  __syncthreads();

  for(int s=0; s<nStages; s++){
    int p = s & 1;
    if(s+1 < nStages){
      int k0 = (s+1)*16;
      #pragma unroll
      for(int i=0;i<2;i++){
        int f = tid + i*256; int row = f>>2, kq = f&3;
        int gk = k0 + kq*4;
        pa[i] = (gk < K) ? *(const float4*)&A[(size_t)(row0+row)*K + gk]
                         : make_float4(0.f,0.f,0.f,0.f);
      }
      #pragma unroll
      for(int i=0;i<2;i++){
        int f = tid + i*256; int kk = f>>5, nq = f&31;
        int gk = k0 + kk, gc = col0 + nq*4;
        pw[i] = (gk < K && gc < N) ? *(const float4*)&W[(size_t)gk*N + gc]
                                   : make_float4(0.f,0.f,0.f,0.f);
      }
    }
    #pragma unroll
    for(int kk=0;kk<16;kk++){
      float4 a0 = *(const float4*)&As[p][kk][ty*4];
      float4 a1 = *(const float4*)&As[p][kk][64 + ty*4];
      ulonglong2 b0 = *(const ulonglong2*)&Ws[p][kk][tx*4];
      ulonglong2 b1 = *(const ulonglong2*)&Ws[p][kk][64 + tx*4];
      unsigned long long bp[4] = {b0.x, b0.y, b1.x, b1.y};
      float a[8] = {a0.x,a0.y,a0.z,a0.w, a1.x,a1.y,a1.z,a1.w};
      #pragma unroll
      for(int i=0;i<8;i++){
        unsigned long long ad = dup_f32(a[i]);
        #pragma unroll
        for(int j=0;j<4;j++) FFMA2(acc2[i][j], ad, bp[j]);
      }
    }
    if(s+1 < nStages){
      int q = (s+1)&1;
      #pragma unroll
      for(int i=0;i<2;i++){
        int f = tid + i*256; int row = f>>2, kq = f&3;
        As[q][kq*4+0][row] = pa[i].x; As[q][kq*4+1][row] = pa[i].y;
        As[q][kq*4+2][row] = pa[i].z; As[q][kq*4+3][row] = pa[i].w;
      }
      #pragma unroll
      for(int i=0;i<2;i++){
        int f = tid + i*256; int kk = f>>5, nq = f&31;
        *(float4*)&Ws[q][kk][nq*4] = pw[i];
      }
      __syncthreads();
    }
  }

  // store: rows ty*4..+3 and 64+ty*4..+3 ; col pairs at tx*4 and 64+tx*4
  #pragma unroll
  for(int i=0;i<8;i++){
    int gr = row0 + ((i<4) ? (ty*4 + i) : (64 + ty*4 + (i-4)));
    #pragma unroll
    for(int j=0;j<4;j++){
      int gc = col0 + ((j<2) ? (tx*4 + 2*j) : (64 + tx*4 + 2*(j-2)));
      if(gc < N){
        float2 c = unpack2(acc2[i][j]);
        float2 o; o.x = c.x + bias[gc]; o.y = c.y + bias[gc+1];
        *(float2*)&C[(size_t)gr*N + gc] = o;
      }
    }
  }
}

// =====================================================================
// QK^T scores (NT GEMM, K=128, FFMA2, 4+4 split), fused 1/sqrt(128)
// =====================================================================
__global__ __launch_bounds__(256) void qk_scores128(
    const float* __restrict__ q, const float* __restrict__ k,
    float* __restrict__ scores)
{
  __shared__ __align__(16) float As[2][16][128];
  __shared__ __align__(16) float Bs[2][16][128];
  int bh = blockIdx.z;
  int b = bh / Hh, h = bh - b*Hh;
  const float* Ab = q + (size_t)b*Ll*DIN + (size_t)h*128;
  const float* Bb2 = k + (size_t)b*Ll*DIN + (size_t)h*128;
  int tid = threadIdx.x;
  int tx = tid & 15, ty = tid >> 4;
  int row0 = blockIdx.y * 128, col0 = blockIdx.x * 128;
  const int nStages = 8; // K=128

  unsigned long long acc2[8][4];
  #pragma unroll
  for(int i=0;i<8;i++)
    #pragma unroll
    for(int j=0;j<4;j++) acc2[i][j] = 0ull;

  float4 pa[2], pb[2];
  {
    #pragma unroll
    for(int i=0;i<2;i++){
      int f = tid + i*256; int row = f>>2, kq = f&3;
      pa[i] = *(const float4*)&Ab[(size_t)(row0+row)*DIN + kq*4];
      pb[i] = *(const float4*)&Bb2[(size_t)(col0+row)*DIN + kq*4];
    }
    #pragma unroll
    for(int i=0;i<2;i++){
      int f = tid + i*256; int row = f>>2, kq = f&3;
      As[0][kq*4+0][row]=pa[i].x; As[0][kq*4+1][row]=pa[i].y;
      As[0][kq*4+2][row]=pa[i].z; As[0][kq*4+3][row]=pa[i].w;
      Bs[0][kq*4+0][row]=pb[i].x; Bs[0][kq*4+1][row]=pb[i].y;
      Bs[0][kq*4+2][row]=pb[i].z; Bs[0][kq*4+3][row]=pb[i].w;
    }
  }
  __syncthreads();

  for(int s=0; s<nStages; s++){
    int p = s & 1;
    if(s+1 < nStages){
      int k0 = (s+1)*16;
      #pragma unroll
      for(int i=0;i<2;i++){
        int f = tid + i*256; int row = f>>2, kq = f&3;
        pa[i] = *(const float4*)&Ab[(size_t)(row0+row)*DIN + k0 + kq*4];
        pb[i] = *(const float4*)&Bb2[(size_t)(col0+row)*DIN + k0 + kq*4];
      }
    }
    #pragma unroll
    for(int kk=0;kk<16;kk++){
      float4 a0 = *(const float4*)&As[p][kk][ty*4];
      float4 a1 = *(const float4*)&As[p][kk][64 + ty*4];
      ulonglong2 b0 = *(const ulonglong2*)&Bs[p][kk][tx*4];
      ulonglong2 b1 = *(const ulonglong2*)&Bs[p][kk][64 + tx*4];
      unsigned long long bp[4] = {b0.x, b0.y, b1.x, b1.y};
      float a[8] = {a0.x,a0.y,a0.z,a0.w, a1.x,a1.y,a1.z,a1.w};
      #pragma unroll
      for(int i=0;i<8;i++){
        unsigned long long ad = dup_f32(a[i]);
        #pragma unroll
        for(int j=0;j<4;j++) FFMA2(acc2[i][j], ad, bp[j]);
      }
    }
    if(s+1 < nStages){
      int qb = (s+1)&1;
      #pragma unroll
      for(int i=0;i<2;i++){
        int f = tid + i*256; int row = f>>2, kq = f&3;
        As[qb][kq*4+0][row]=pa[i].x; As[qb][kq*4+1][row]=pa[i].y;
        As[qb][kq*4+2][row]=pa[i].z; As[qb][kq*4+3][row]=pa[i].w;
        Bs[qb][kq*4+0][row]=pb[i].x; Bs[qb][kq*4+1][row]=pb[i].y;
        Bs[qb][kq*4+2][row]=pb[i].z; Bs[qb][kq*4+3][row]=pb[i].w;
      }
      __syncthreads();
    }
  }

  const float scale = 0.08838834764831845f; // 1/sqrt(128)
  #pragma unroll
  for(int i=0;i<8;i++){
    int gl = row0 + ((i<4) ? (ty*4 + i) : (64 + ty*4 + (i-4)));
    #pragma unroll
    for(int j=0;j<4;j++){
      int gm = col0 + ((j<2) ? (tx*4 + 2*j) : (64 + tx*4 + 2*(j-2)));
      float2 c = unpack2(acc2[i][j]);
      float2 o; o.x = c.x * scale; o.y = c.y * scale;
      *(float2*)&scores[((size_t)bh*Ll + gl)*Ll + gm] = o;
    }
  }
}

// ---------------- softmax over m per (b,l), all 6 heads batched ----------------
__global__ __launch_bounds__(256) void softmax_mean_kernel(
    const float* __restrict__ scores, float* __restrict__ pattn)
{
  __shared__ float red1[Hh][8];
  __shared__ float r1[Hh];
  __shared__ float red2[Hh][8];
  __shared__ float r2[Hh];
  int bl = blockIdx.x;
  int b = bl >> 8, l = bl & 255;
  int m = threadIdx.x, w = m >> 5, lane = m & 31;
  const float* base = scores + ((size_t)(b*Hh)*Ll + l)*Ll + m;
  float s[Hh];
  #pragma unroll
  for(int h=0;h<Hh;h++) s[h] = base[(size_t)h*Ll*Ll];

  float v[Hh];
  #pragma unroll
  for(int h=0;h<Hh;h++){
    v[h] = s[h];
    #pragma unroll
    for(int o=16;o;o>>=1) v[h] = fmaxf(v[h], __shfl_xor_sync(0xffffffffu, v[h], o));
  }
  if(lane == 0){
    #pragma unroll
    for(int h=0;h<Hh;h++) red1[h][w] = v[h];
  }
  __syncthreads();
  if(m < Hh){
    float x = red1[m][0];
    #pragma unroll
    for(int j=1;j<8;j++) x = fmaxf(x, red1[m][j]);
    r1[m] = x;
  }
  __syncthreads();

  float e[Hh];
  #pragma unroll
  for(int h=0;h<Hh;h++){
    e[h] = expf(s[h] - r1[h]);
    v[h] = e[h];
    #pragma unroll
    for(int o=16;o;o>>=1) v[h] += __shfl_xor_sync(0xffffffffu, v[h], o);
  }
  if(lane == 0){
    #pragma unroll
    for(int h=0;h<Hh;h++) red2[h][w] = v[h];
  }
  __syncthreads();
  if(m < Hh){
    float x = red2[m][0];
    #pragma unroll
    for(int j=1;j<8;j++) x += red2[m][j];
    r2[m] = x;
  }
  __syncthreads();

  float acc = 0.f;
  #pragma unroll
  for(int h=0;h<Hh;h++) acc += e[h] / r2[h];
  pattn[(size_t)bl*Ll + m] = acc * (1.f/6.f);
}

// ---------------- exact 1024th-largest per batch via radix select ----------------
__global__ __launch_bounds__(1024) void topk_select_kernel(
    const float* __restrict__ pattn, float* __restrict__ kth)
{
  int b = blockIdx.x;
  int tid = threadIdx.x;
  const unsigned* v = (const unsigned*)(pattn + (size_t)b*Ll*Ll);
  __shared__ unsigned hist[256];
  __shared__ unsigned s_prefix;
  __shared__ int s_k;
  if(tid == 0){ s_prefix = 0u; s_k = TOPK; }
  __syncthreads();
  for(int pass=3; pass>=0; --pass){
    int shift = pass*8;
    if(tid < 256) hist[tid] = 0u;
    __syncthreads();
    unsigned prefix = s_prefix;
    unsigned mask = (pass==3) ? 0u : (0xFFFFFFFFu << ((pass+1)*8));
    for(int i=tid; i<Ll*Ll; i+=1024){
      unsigned x = v[i];
      if((x & mask) == prefix) atomicAdd(&hist[(x >> shift) & 0xFF], 1u);
    }
    __syncthreads();
    if(tid == 0){
      int k = s_k, cum = 0;
      unsigned byte = 0;
      for(int bb=255; bb>=0; --bb){
        int c = (int)hist[bb];
        if(cum + c >= k){ byte = (unsigned)bb; s_k = k - cum; break; }
        cum += c;
      }
      s_prefix = prefix | (byte << shift);
    }
    __syncthreads();
  }
  if(tid == 0) kth[b] = __uint_as_float(s_prefix);
}

// ---------------- adjacency mask: diag | sel | sel^T ----------------
__global__ __launch_bounds__(256) void build_adj_kernel(
    const float* __restrict__ pattn, const float* __restrict__ kth,
    unsigned char* __restrict__ adj)
{
  int b = blockIdx.x >> 8, i = blockIdx.x & 255, j = threadIdx.x;
  float t = kth[b];
  const float* p = pattn + (size_t)b*Ll*Ll;
  bool e = (i==j) || (p[(size_t)i*Ll + j] >= t) || (p[(size_t)j*Ll + i] >= t);
  adj[(size_t)b*Ll*Ll + (size_t)i*Ll + j] = e ? 1 : 0;
}

// ---------------- repack Wh(layer,h,d,k) -> Wcat(layer, d, h*50+k) ----------------
__global__ void repack_wh_kernel(const float* __restrict__ Wh, float* __restrict__ wcat){
  int idx = blockIdx.x*blockDim.x + threadIdx.x;
  if(idx >= NLAYERS*Hh*MEMD*DKk) return;
  int layer = idx / (Hh*MEMD*DKk);
  int r = idx - layer*(Hh*MEMD*DKk);
  int h = r / (MEMD*DKk);
  int r2 = r - h*(MEMD*DKk);
  int d = r2 / DKk;
  int kk = r2 - d*DKk;
  wcat[(size_t)layer*MEMD*MEMD + (size_t)d*MEMD + h*DKk + kk] = Wh[idx];
}

// ---------------- s_i, s_j per (b,h,l) ----------------
__global__ void sisj_kernel(const float* __restrict__ proj, const float* __restrict__ awl,
                            float* __restrict__ si, float* __restrict__ sj)
{
  int idx = blockIdx.x*blockDim.x + threadIdx.x;
  if(idx >= Bb*Hh*Ll) return;
  int b = idx / (Hh*Ll);
  int r = idx - b*(Hh*Ll);
  int h = r / Ll;
  int l = r - h*Ll;
  const float* pr = proj + (((size_t)(b*Ll + l))*Hh + h)*DKk;
  const float* w1 = awl;
  const float* w2 = awl + DKk;
  float a = 0.f, c = 0.f;
  #pragma unroll
  for(int k2=0;k2<DKk;k2++){ float pv = pr[k2]; a = fmaf(pv, w1[k2], a); c = fmaf(pv, w2[k2], c); }
  si[idx] = a; sj[idx] = c;
}

// =====================================================================
// fused GAT attention: block per (b,h,half). Two-phase chunked:
//  phase1: warp-private softmax for 4 rows/warp -> Psm[32][256]
//  phase2: blocked AV GEMM (P[32x256] @ V[256x50]) with FFMA2
// smem: projS[256*50] + Psm[32*256] + sjS[256] + siS[128] = 85504 B
// =====================================================================
__global__ __launch_bounds__(256) void gat_attn_kernel(
    const float* __restrict__ proj, const float* __restrict__ si, const float* __restrict__ sj,
    const unsigned char* __restrict__ adj, const float* __restrict__ abp,
    float* __restrict__ cat)
{
  extern __shared__ float smx[];
  float* projS = smx;                   // 12800
  float* Psm   = projS + Ll*DKk;        // 8192
  float* sjS   = Psm + 32*Ll;           // 256
  float* siS   = sjS + Ll;              // 128

  int bhh = blockIdx.x;
  int bh = bhh >> 1, half = bhh & 1;
  int b = bh / Hh, h = bh - b*Hh;
  int tid = threadIdx.x;
  int lane = tid & 31, w = tid >> 5;

  // stage proj slice for this head: projS[m*50+k] (float2 loads)
  {
    const float* projBase = proj + ((size_t)(b*Ll))*MEMD + h*DKk;
    float2* dst = (float2*)projS;
    for(int e=tid; e<Ll*25; e+=256){
      int m = e / 25, t = e - m*25;
      dst[m*25+t] = ((const float2*)(projBase + (size_t)m*MEMD))[t];
    }
  }
  sjS[tid] = sj[(size_t)bh*Ll + tid];
  if(tid < 128) siS[tid] = si[(size_t)bh*Ll + half*128 + tid];
  __syncthreads();

  float abv = abp[0];
  const unsigned char* adjb = adj + (size_t)b*Ll*Ll;

  for(int c=0; c<4; c++){
    // ---- phase 1: softmax for 32 rows (warp w does rows w*4..w*4+3) ----
    #pragma unroll
    for(int rr=0; rr<4; rr++){
      int pr = w*4 + rr;
      int l = half*128 + c*32 + pr;
      float si_l = siS[c*32 + pr];
      const unsigned char* arow = adjb + (size_t)l*Ll;
      float pv[8]; bool okv[8];
      float mx = -3.0e38f;
      #pragma unroll
      for(int j=0;j<8;j++){
        int m = lane + j*32;
        float sval = si_l + sjS[m] + abv;
        sval = (sval > 0.f) ? sval : 0.2f*sval;
        bool ok = arow[m] != 0;
        okv[j] = ok; pv[j] = sval;
        mx = fmaxf(mx, ok ? sval : -3.0e38f);
      }
      #pragma unroll
      for(int o=16;o;o>>=1) mx = fmaxf(mx, __shfl_xor_sync(0xffffffffu, mx, o));
      float ev[8];
      float s = 0.f;
      #pragma unroll
      for(int j=0;j<8;j++){
        ev[j] = okv[j] ? expf(pv[j] - mx) : 0.f;
        s += ev[j];
      }
      #pragma unroll
      for(int o=16;o;o>>=1) s += __shfl_xor_sync(0xffffffffu, s, o);
      float inv = 1.0f / s;
      #pragma unroll
      for(int j=0;j<8;j++)
        Psm[pr*Ll + lane + j*32] = ev[j] * inv;
    }
    __syncthreads();

    // ---- phase 2: AV += P[32x256] @ V[256x50] ; lane<25 owns col pair 'lane',
    //      warp w owns rows {w, w+8, w+16, w+24} of the chunk ----
    if(lane < 25){
      unsigned long long acc[4] = {0ull,0ull,0ull,0ull};
      const unsigned long long* Vp = (const unsigned long long*)projS;
      #pragma unroll 4
      for(int m=0; m<Ll; m++){
        unsigned long long bv = Vp[m*25 + lane];
        #pragma unroll
        for(int t=0;t<4;t++){
          float pt = Psm[(w + 8*t)*Ll + m];
          FFMA2(acc[t], dup_f32(pt), bv);
        }
      }
      #pragma unroll
      for(int t=0;t<4;t++){
        int pr = w + 8*t;
        int l = half*128 + c*32 + pr;
        float2 o = unpack2(acc[t]);
        *(float2*)&cat[((size_t)(b*Ll + l))*MEMD + h*DKk + lane*2] = o;
      }
    }
    __syncthreads();
  }
}

// ---------------- res = h + cat; LayerNorm -> h (in place) ----------------
__global__ __launch_bounds__(256) void add_ln_kernel(
    float* __restrict__ hbuf, const float* __restrict__ cat,
    const float* __restrict__ g, const float* __restrict__ bln)
{
  __shared__ float rbuf[MEMD];
  __shared__ float red[8];
  int row = blockIdx.x, tid = threadIdx.x;
  float s = 0.f;
  for(int d=tid; d<MEMD; d+=256){
    float r = hbuf[(size_t)row*MEMD + d] + cat[(size_t)row*MEMD + d];
    rbuf[d] = r; s += r;
  }
  s = blockSum256(s, red);
  float mu = s * (1.f/MEMD);
  float v = 0.f;
  for(int d=tid; d<MEMD; d+=256){ float r = rbuf[d] - mu; v = fmaf(r, r, v); }
  v = blockSum256(v, red);
  float inv = 1.0f / sqrtf(v*(1.f/MEMD) + 1e-5f);
  for(int d=tid; d<MEMD; d+=256)
    hbuf[(size_t)row*MEMD + d] = (rbuf[d] - mu) * inv * g[d] + bln[d];
}

// ---------------- pooled = mean_l h; out = pooled @ Wc + bc ----------------
__global__ __launch_bounds__(256) void pool_classify_kernel(
    const float* __restrict__ hbuf, const float* __restrict__ Wc,
    const float* __restrict__ bc, float* __restrict__ out)
{
  __shared__ float pooled[MEMD];
  __shared__ float red[8];
  int b = blockIdx.x, tid = threadIdx.x;
  for(int d=tid; d<MEMD; d+=256){
    float s = 0.f;
    for(int l=0; l<Ll; l++) s += hbuf[((size_t)(b*Ll + l))*MEMD + d];
    pooled[d] = s * (1.f/Ll);
  }
  __syncthreads();
  for(int c=0; c<NCc; c++){
    float p = 0.f;
    for(int d=tid; d<MEMD; d+=256) p = fmaf(pooled[d], Wc[d*NCc + c], p);
    p = blockSum256(p, red);
    if(tid == 0) out[b*NCc + c] = p + bc[c];
  }
}

// ---------------- launcher ----------------
extern "C" void kernel_launch(void* const* d_in, const int* in_sizes, int n_in,
                              void* d_out, int out_size)
{
  const float* x    = (const float*)d_in[0];
  const float* wq   = (const float*)d_in[1];
  const float* bq   = (const float*)d_in[2];
  const float* wk   = (const float*)d_in[3];
  const float* bk   = (const float*)d_in[4];
  const float* w_in = (const float*)d_in[5];
  const float* b_in = (const float*)d_in[6];
  const float* Wh   = (const float*)d_in[7];
  const float* bh   = (const float*)d_in[8];
  const float* aw   = (const float*)d_in[9];
  const float* ab   = (const float*)d_in[10];
  const float* g_ln = (const float*)d_in[11];
  const float* b_ln = (const float*)d_in[12];
  const float* Wc   = (const float*)d_in[13];
  const float* bc   = (const float*)d_in[14];
  float* out = (float*)d_out;

  float *pq, *pk, *pscores, *ppattn, *pkth, *ph, *pproj, *pcat, *psi, *psj, *pwcat;
  unsigned char* padj;
  cudaGetSymbolAddress((void**)&pq, g_q);
  cudaGetSymbolAddress((void**)&pk, g_k);
  cudaGetSymbolAddress((void**)&pscores, g_scores);
  cudaGetSymbolAddress((void**)&ppattn, g_pattn);
  cudaGetSymbolAddress((void**)&pkth, g_kth);
  cudaGetSymbolAddress((void**)&padj, g_adj);
  cudaGetSymbolAddress((void**)&ph, g_h);
  cudaGetSymbolAddress((void**)&pproj, g_proj);
  cudaGetSymbolAddress((void**)&pcat, g_cat);
  cudaGetSymbolAddress((void**)&psi, g_si);
  cudaGetSymbolAddress((void**)&psj, g_sj);
  cudaGetSymbolAddress((void**)&pwcat, g_wcat);

  const int ATTN_SMEM = (Ll*DKk + 32*Ll + Ll + 128) * 4; // 85504 bytes
  cudaFuncSetAttribute(gat_attn_kernel, cudaFuncAttributeMaxDynamicSharedMemorySize, ATTN_SMEM);

  // q, k projections
  sgemm128db<<<dim3(DIN/128, BL/128), 256>>>(x, wq, bq, pq, BL, DIN, DIN);
  sgemm128db<<<dim3(DIN/128, BL/128), 256>>>(x, wk, bk, pk, BL, DIN, DIN);

  // scores + softmax + head-mean
  qk_scores128<<<dim3(2, 2, Bb*Hh), 256>>>(pq, pk, pscores);
  softmax_mean_kernel<<<Bb*Ll, 256>>>(pscores, ppattn);

  // top-k threshold + adjacency
  topk_select_kernel<<<Bb, 1024>>>(ppattn, pkth);
  build_adj_kernel<<<Bb*Ll, 256>>>(ppattn, pkth, padj);

  // h = x @ w_in + b_in
  sgemm128db<<<dim3((MEMD+127)/128, BL/128), 256>>>(x, w_in, b_in, ph, BL, MEMD, DIN);

  // repack Wh into (layer, MEM, H*DK)
  repack_wh_kernel<<<(NLAYERS*Hh*MEMD*DKk + 255)/256, 256>>>(Wh, pwcat);

  for(int layer=0; layer<NLAYERS; layer++){
    sgemm128db<<<dim3((MEMD+127)/128, BL/128), 256>>>(
        ph, pwcat + (size_t)layer*MEMD*MEMD, bh + layer*MEMD, pproj, BL, MEMD, MEMD);
    sisj_kernel<<<(Bb*Hh*Ll + 127)/128, 128>>>(pproj, aw + layer*2*DKk, psi, psj);
    gat_attn_kernel<<<Bb*Hh*2, 256, ATTN_SMEM>>>(pproj, psi, psj, padj, ab + layer, pcat);
    add_ln_kernel<<<Bb*Ll, 256>>>(ph, pcat, g_ln + layer*MEMD, b_ln + layer*MEMD);
  }

  pool_classify_kernel<<<Bb, 256>>>(ph, Wc, bc, out);
}

// round 5
// speedup vs baseline: 2.2010x; 1.1284x over previous
#include <cuda_runtime.h>
#include <math.h>

#define Bb 64
#define Ll 256
#define DIN 768
#define MEMD 300
#define Hh 6
#define TOPK 1024
#define NCc 3
#define NLAYERS 2
#define DKk 50
#define BL (Bb*Ll)   // 16384

// ---------------- scratch (device globals; no runtime allocation) ----------------
__device__ float g_q[BL*DIN];                 // 50 MB
__device__ float g_k[BL*DIN];                 // 50 MB
__device__ float g_scores[Bb*Hh*Ll*Ll];       // 100 MB
__device__ float g_pattn[Bb*Ll*Ll];           // 16.8 MB
__device__ float g_kth[Bb];
__device__ unsigned char g_adj[Bb*Ll*Ll];     // 4.2 MB
__device__ float g_h[BL*MEMD];                // 19.7 MB
__device__ float g_proj[BL*MEMD];             // 19.7 MB
__device__ float g_cat[BL*MEMD];              // 19.7 MB
__device__ float g_si[Bb*Hh*Ll];
__device__ float g_sj[Bb*Hh*Ll];
__device__ float g_wcat[NLAYERS*MEMD*MEMD];   // repacked Wh

// ---------------- packed fp32x2 FMA helpers (Blackwell) ----------------
#define FFMA2(acc, a2, b2) \
  asm("fma.rn.f32x2 %0, %1, %2, %3;" : "=l"(acc) : "l"(a2), "l"(b2), "l"(acc))

__device__ __forceinline__ unsigned long long dup_f32(float x){
  unsigned long long r;
  asm("mov.b64 %0, {%1, %1};" : "=l"(r) : "f"(x));
  return r;
}
__device__ __forceinline__ float2 unpack2(unsigned long long v){
  float2 c;
  asm("mov.b64 {%0, %1}, %2;" : "=f"(c.x), "=f"(c.y) : "l"(v));
  return c;
}

// ---------------- tf32 helpers ----------------
__device__ __forceinline__ unsigned f2tf32(float x){
  unsigned r; asm("cvt.rna.tf32.f32 %0, %1;" : "=r"(r) : "f"(x)); return r;
}
__device__ __forceinline__ void cvt_hilo(float v, float& h, float& l){
  unsigned hu = f2tf32(v);
  float hf = __uint_as_float(hu);
  h = hf;
  l = __uint_as_float(f2tf32(v - hf));
}
__device__ __forceinline__ void mma_tf32(float* d, const unsigned* a, const unsigned* b){
  asm("mma.sync.aligned.m16n8k8.row.col.f32.tf32.tf32.f32 "
      "{%0,%1,%2,%3},{%4,%5,%6,%7},{%8,%9},{%0,%1,%2,%3};"
      : "+f"(d[0]), "+f"(d[1]), "+f"(d[2]), "+f"(d[3])
      : "r"(a[0]), "r"(a[1]), "r"(a[2]), "r"(a[3]), "r"(b[0]), "r"(b[1]));
}

// ---------------- reduction helpers ----------------
__device__ __forceinline__ float warpSum(float v){
  #pragma unroll
  for(int o=16;o;o>>=1) v += __shfl_xor_sync(0xffffffffu, v, o);
  return v;
}
__device__ __forceinline__ float blockSum256(float v, float* sh){
  v = warpSum(v);
  int w = threadIdx.x >> 5;
  if((threadIdx.x & 31) == 0) sh[w] = v;
  __syncthreads();
  if(threadIdx.x < 8){
    float x = sh[threadIdx.x];
    #pragma unroll
    for(int o=4;o;o>>=1) x += __shfl_xor_sync(0xffu, x, o);
    if(threadIdx.x==0) sh[0] = x;
  }
  __syncthreads();
  float r = sh[0];
  __syncthreads();
  return r;
}

// =====================================================================
// 3xTF32 tensor-core GEMM: C[M,N] = A[M,K] @ W[K,N] + bias
// Block 128x128, BK=16, 8 warps (4x2), warp tile 32x64, m16n8k8 mma.
// Error ~2^-22 relative (lo*lo dropped) — near-fp32.
// smem: Ahi/Alo [2][128][20], Whi/Wlo [2][16][136]  = 75776 B dynamic.
// =====================================================================
#define GEMM_ASZ 2560   // 128*20
#define GEMM_WSZ 2176   // 16*136
#define GEMM_SMEM ((2*GEMM_ASZ*2 + 2*GEMM_WSZ*2)*4)  // 75776

__global__ __launch_bounds__(256) void gemm_tf32x3(
    const float* __restrict__ A, const float* __restrict__ W,
    const float* __restrict__ bias, float* __restrict__ C,
    int M, int N, int K)
{
  extern __shared__ float smdyn[];
  float* Ahi = smdyn;                 // [2][GEMM_ASZ]
  float* Alo = Ahi + 2*GEMM_ASZ;
  float* Whi = Alo + 2*GEMM_ASZ;      // [2][GEMM_WSZ]
  float* Wlo = Whi + 2*GEMM_WSZ;

  int tid = threadIdx.x, lane = tid & 31, wid = tid >> 5;
  int wm = wid & 3, wn = wid >> 2;    // 4 x 2 warp grid
  int row0 = blockIdx.y*128, col0 = blockIdx.x*128;
  int nStages = (K + 15) >> 4;

  float acc[2][8][4];
  #pragma unroll
  for(int i=0;i<2;i++)
    #pragma unroll
    for(int j=0;j<8;j++)
      #pragma unroll
      for(int t=0;t<4;t++) acc[i][j][t] = 0.f;

  float4 pa[2], pw[2];

  // ---- stage loader (global -> regs) ----
  #define GLOAD(k0)                                                         \
    {                                                                       \
      _Pragma("unroll")                                                     \
      for(int i=0;i<2;i++){                                                 \
        int f = tid + i*256; int m = f>>2, q = f&3;                         \
        int gk = (k0) + q*4;                                                \
        pa[i] = (gk < K) ? *(const float4*)&A[(size_t)(row0+m)*K + gk]      \
                         : make_float4(0.f,0.f,0.f,0.f);                    \
      }                                                                     \
      _Pragma("unroll")                                                     \
      for(int i=0;i<2;i++){                                                 \
        int f = tid + i*256; int kk = f>>5, n4 = f&31;                      \
        int gk = (k0) + kk, gc = col0 + n4*4;                               \
        pw[i] = (gk < K && gc < N) ? *(const float4*)&W[(size_t)gk*N + gc]  \
                                   : make_float4(0.f,0.f,0.f,0.f);          \
      }                                                                     \
    }

  // ---- stage storer (regs -> smem, with hi/lo tf32 split) ----
  #define SSTORE(p)                                                         \
    {                                                                       \
      _Pragma("unroll")                                                     \
      for(int i=0;i<2;i++){                                                 \
        int f = tid + i*256; int m = f>>2, q = f&3;                         \
        float4 v = pa[i]; float4 h, l;                                      \
        cvt_hilo(v.x, h.x, l.x); cvt_hilo(v.y, h.y, l.y);                   \
        cvt_hilo(v.z, h.z, l.z); cvt_hilo(v.w, h.w, l.w);                   \
        *(float4*)&Ahi[(p)*GEMM_ASZ + m*20 + q*4] = h;                      \
        *(float4*)&Alo[(p)*GEMM_ASZ + m*20 + q*4] = l;                      \
      }                                                                     \
      _Pragma("unroll")                                                     \
      for(int i=0;i<2;i++){                                                 \
        int f = tid + i*256; int kk = f>>5, n4 = f&31;                      \
        float4 v = pw[i]; float4 h, l;                                      \
        cvt_hilo(v.x, h.x, l.x); cvt_hilo(v.y, h.y, l.y);                   \
        cvt_hilo(v.z, h.z, l.z); cvt_hilo(v.w, h.w, l.w);                   \
        *(float4*)&Whi[(p)*GEMM_WSZ + kk*136 + n4*4] = h;                   \
        *(float4*)&Wlo[(p)*GEMM_WSZ + kk*136 + n4*4] = l;                   \
      }                                                                     \
    }

  GLOAD(0);
  SSTORE(0);
  __syncthreads();

  for(int s=0; s<nStages; s++){
    int p = s & 1;
    if(s+1 < nStages) GLOAD((s+1)*16);

    const float* Ah = Ahi + p*GEMM_ASZ;
    const float* Al = Alo + p*GEMM_ASZ;
    const float* Wh = Whi + p*GEMM_WSZ;
    const float* Wl = Wlo + p*GEMM_WSZ;

    #pragma unroll
    for(int k8=0; k8<16; k8+=8){
      int kA = k8 + (lane & 3);
      int mb = wm*32 + (lane >> 2);
      unsigned ah[2][4], al[2][4];
      #pragma unroll
      for(int mt=0; mt<2; mt++){
        int m0 = (mb + mt*16)*20;
        ah[mt][0] = __float_as_uint(Ah[m0 + kA]);
        ah[mt][1] = __float_as_uint(Ah[m0 + 160 + kA]);
        ah[mt][2] = __float_as_uint(Ah[m0 + kA + 4]);
        ah[mt][3] = __float_as_uint(Ah[m0 + 160 + kA + 4]);
        al[mt][0] = __float_as_uint(Al[m0 + kA]);
        al[mt][1] = __float_as_uint(Al[m0 + 160 + kA]);
        al[mt][2] = __float_as_uint(Al[m0 + kA + 4]);
        al[mt][3] = __float_as_uint(Al[m0 + 160 + kA + 4]);
      }
      int nb = wn*64 + (lane >> 2);
      int kB = (k8 + (lane & 3))*136;
      unsigned bh[8][2], bl[8][2];
      #pragma unroll
      for(int nt=0; nt<8; nt++){
        bh[nt][0] = __float_as_uint(Wh[kB + nb + nt*8]);
        bh[nt][1] = __float_as_uint(Wh[kB + 4*136 + nb + nt*8]);
        bl[nt][0] = __float_as_uint(Wl[kB + nb + nt*8]);
        bl[nt][1] = __float_as_uint(Wl[kB + 4*136 + nb + nt*8]);
      }
      #pragma unroll
      for(int mt=0; mt<2; mt++)
        #pragma unroll
        for(int nt=0; nt<8; nt++){
          mma_tf32(acc[mt][nt], ah[mt], bh[nt]);
          mma_tf32(acc[mt][nt], ah[mt], bl[nt]);
          mma_tf32(acc[mt][nt], al[mt], bh[nt]);
        }
    }

    if(s+1 < nStages){
      SSTORE((s+1)&1);
      __syncthreads();
    }
  }

  // epilogue
  #pragma unroll
  for(int mt=0; mt<2; mt++){
    int r0 = row0 + wm*32 + mt*16 + (lane >> 2);
    #pragma unroll
    for(int nt=0; nt<8; nt++){
      int c = col0 + wn*64 + nt*8 + (lane & 3)*2;
      if(c < N){
        float2 bs = *(const float2*)&bias[c];
        float2 o0; o0.x = acc[mt][nt][0] + bs.x; o0.y = acc[mt][nt][1] + bs.y;
        *(float2*)&C[(size_t)r0*N + c] = o0;
        float2 o1; o1.x = acc[mt][nt][2] + bs.x; o1.y = acc[mt][nt][3] + bs.y;
        *(float2*)&C[(size_t)(r0+8)*N + c] = o1;
      }
    }
  }
  #undef GLOAD
  #undef SSTORE
}

// =====================================================================
// QK^T scores (NT GEMM, K=128, FFMA2, 4+4 split), fused 1/sqrt(128)
// =====================================================================
__global__ __launch_bounds__(256) void qk_scores128(
    const float* __restrict__ q, const float* __restrict__ k,
    float* __restrict__ scores)
{
  __shared__ __align__(16) float As[2][16][128];
  __shared__ __align__(16) float Bs[2][16][128];
  int bh = blockIdx.z;
  int b = bh / Hh, h = bh - b*Hh;
  const float* Ab = q + (size_t)b*Ll*DIN + (size_t)h*128;
  const float* Bb2 = k + (size_t)b*Ll*DIN + (size_t)h*128;
  int tid = threadIdx.x;
  int tx = tid & 15, ty = tid >> 4;
  int row0 = blockIdx.y * 128, col0 = blockIdx.x * 128;
  const int nStages = 8; // K=128

  unsigned long long acc2[8][4];
  #pragma unroll
  for(int i=0;i<8;i++)
    #pragma unroll
    for(int j=0;j<4;j++) acc2[i][j] = 0ull;

  float4 pa[2], pb[2];
  {
    #pragma unroll
    for(int i=0;i<2;i++){
      int f = tid + i*256; int row = f>>2, kq = f&3;
      pa[i] = *(const float4*)&Ab[(size_t)(row0+row)*DIN + kq*4];
      pb[i] = *(const float4*)&Bb2[(size_t)(col0+row)*DIN + kq*4];
    }
    #pragma unroll
    for(int i=0;i<2;i++){
      int f = tid + i*256; int row = f>>2, kq = f&3;
      As[0][kq*4+0][row]=pa[i].x; As[0][kq*4+1][row]=pa[i].y;
      As[0][kq*4+2][row]=pa[i].z; As[0][kq*4+3][row]=pa[i].w;
      Bs[0][kq*4+0][row]=pb[i].x; Bs[0][kq*4+1][row]=pb[i].y;
      Bs[0][kq*4+2][row]=pb[i].z; Bs[0][kq*4+3][row]=pb[i].w;
    }
  }
  __syncthreads();

  for(int s=0; s<nStages; s++){
    int p = s & 1;
    if(s+1 < nStages){
      int k0 = (s+1)*16;
      #pragma unroll
      for(int i=0;i<2;i++){
        int f = tid + i*256; int row = f>>2, kq = f&3;
        pa[i] = *(const float4*)&Ab[(size_t)(row0+row)*DIN + k0 + kq*4];
        pb[i] = *(const float4*)&Bb2[(size_t)(col0+row)*DIN + k0 + kq*4];
      }
    }
    #pragma unroll
    for(int kk=0;kk<16;kk++){
      float4 a0 = *(const float4*)&As[p][kk][ty*4];
      float4 a1 = *(const float4*)&As[p][kk][64 + ty*4];
      ulonglong2 b0 = *(const ulonglong2*)&Bs[p][kk][tx*4];
      ulonglong2 b1 = *(const ulonglong2*)&Bs[p][kk][64 + tx*4];
      unsigned long long bp[4] = {b0.x, b0.y, b1.x, b1.y};
      float a[8] = {a0.x,a0.y,a0.z,a0.w, a1.x,a1.y,a1.z,a1.w};
      #pragma unroll
      for(int i=0;i<8;i++){
        unsigned long long ad = dup_f32(a[i]);
        #pragma unroll
        for(int j=0;j<4;j++) FFMA2(acc2[i][j], ad, bp[j]);
      }
    }
    if(s+1 < nStages){
      int qb = (s+1)&1;
      #pragma unroll
      for(int i=0;i<2;i++){
        int f = tid + i*256; int row = f>>2, kq = f&3;
        As[qb][kq*4+0][row]=pa[i].x; As[qb][kq*4+1][row]=pa[i].y;
        As[qb][kq*4+2][row]=pa[i].z; As[qb][kq*4+3][row]=pa[i].w;
        Bs[qb][kq*4+0][row]=pb[i].x; Bs[qb][kq*4+1][row]=pb[i].y;
        Bs[qb][kq*4+2][row]=pb[i].z; Bs[qb][kq*4+3][row]=pb[i].w;
      }
      __syncthreads();
    }
  }

  const float scale = 0.08838834764831845f; // 1/sqrt(128)
  #pragma unroll
  for(int i=0;i<8;i++){
    int gl = row0 + ((i<4) ? (ty*4 + i) : (64 + ty*4 + (i-4)));
    #pragma unroll
    for(int j=0;j<4;j++){
      int gm = col0 + ((j<2) ? (tx*4 + 2*j) : (64 + tx*4 + 2*(j-2)));
      float2 c = unpack2(acc2[i][j]);
      float2 o; o.x = c.x * scale; o.y = c.y * scale;
      *(float2*)&scores[((size_t)bh*Ll + gl)*Ll + gm] = o;
    }
  }
}

// ---------------- softmax over m per (b,l), all 6 heads batched ----------------
__global__ __launch_bounds__(256) void softmax_mean_kernel(
    const float* __restrict__ scores, float* __restrict__ pattn)
{
  __shared__ float red1[Hh][8];
  __shared__ float r1[Hh];
  __shared__ float red2[Hh][8];
  __shared__ float r2[Hh];
  int bl = blockIdx.x;
  int b = bl >> 8, l = bl & 255;
  int m = threadIdx.x, w = m >> 5, lane = m & 31;
  const float* base = scores + ((size_t)(b*Hh)*Ll + l)*Ll + m;
  float s[Hh];
  #pragma unroll
  for(int h=0;h<Hh;h++) s[h] = base[(size_t)h*Ll*Ll];

  float v[Hh];
  #pragma unroll
  for(int h=0;h<Hh;h++){
    v[h] = s[h];
    #pragma unroll
    for(int o=16;o;o>>=1) v[h] = fmaxf(v[h], __shfl_xor_sync(0xffffffffu, v[h], o));
  }
  if(lane == 0){
    #pragma unroll
    for(int h=0;h<Hh;h++) red1[h][w] = v[h];
  }
  __syncthreads();
  if(m < Hh){
    float x = red1[m][0];
    #pragma unroll
    for(int j=1;j<8;j++) x = fmaxf(x, red1[m][j]);
    r1[m] = x;
  }
  __syncthreads();

  float e[Hh];
  #pragma unroll
  for(int h=0;h<Hh;h++){
    e[h] = expf(s[h] - r1[h]);
    v[h] = e[h];
    #pragma unroll
    for(int o=16;o;o>>=1) v[h] += __shfl_xor_sync(0xffffffffu, v[h], o);
  }
  if(lane == 0){
    #pragma unroll
    for(int h=0;h<Hh;h++) red2[h][w] = v[h];
  }
  __syncthreads();
  if(m < Hh){
    float x = red2[m][0];
    #pragma unroll
    for(int j=1;j<8;j++) x += red2[m][j];
    r2[m] = x;
  }
  __syncthreads();

  float acc = 0.f;
  #pragma unroll
  for(int h=0;h<Hh;h++) acc += e[h] / r2[h];
  pattn[(size_t)bl*Ll + m] = acc * (1.f/6.f);
}

// ---------------- exact 1024th-largest per batch via radix select ----------------
__global__ __launch_bounds__(1024) void topk_select_kernel(
    const float* __restrict__ pattn, float* __restrict__ kth)
{
  int b = blockIdx.x;
  int tid = threadIdx.x;
  const unsigned* v = (const unsigned*)(pattn + (size_t)b*Ll*Ll);
  __shared__ unsigned hist[256];
  __shared__ unsigned s_prefix;
  __shared__ int s_k;
  if(tid == 0){ s_prefix = 0u; s_k = TOPK; }
  __syncthreads();
  for(int pass=3; pass>=0; --pass){
    int shift = pass*8;
    if(tid < 256) hist[tid] = 0u;
    __syncthreads();
    unsigned prefix = s_prefix;
    unsigned mask = (pass==3) ? 0u : (0xFFFFFFFFu << ((pass+1)*8));
    for(int i=tid; i<Ll*Ll; i+=1024){
      unsigned x = v[i];
      if((x & mask) == prefix) atomicAdd(&hist[(x >> shift) & 0xFF], 1u);
    }
    __syncthreads();
    if(tid == 0){
      int k = s_k, cum = 0;
      unsigned byte = 0;
      for(int bb=255; bb>=0; --bb){
        int c = (int)hist[bb];
        if(cum + c >= k){ byte = (unsigned)bb; s_k = k - cum; break; }
        cum += c;
      }
      s_prefix = prefix | (byte << shift);
    }
    __syncthreads();
  }
  if(tid == 0) kth[b] = __uint_as_float(s_prefix);
}

// ---------------- adjacency mask: diag | sel | sel^T ----------------
__global__ __launch_bounds__(256) void build_adj_kernel(
    const float* __restrict__ pattn, const float* __restrict__ kth,
    unsigned char* __restrict__ adj)
{
  int b = blockIdx.x >> 8, i = blockIdx.x & 255, j = threadIdx.x;
  float t = kth[b];
  const float* p = pattn + (size_t)b*Ll*Ll;
  bool e = (i==j) || (p[(size_t)i*Ll + j] >= t) || (p[(size_t)j*Ll + i] >= t);
  adj[(size_t)b*Ll*Ll + (size_t)i*Ll + j] = e ? 1 : 0;
}

// ---------------- repack Wh(layer,h,d,k) -> Wcat(layer, d, h*50+k) ----------------
__global__ void repack_wh_kernel(const float* __restrict__ Wh, float* __restrict__ wcat){
  int idx = blockIdx.x*blockDim.x + threadIdx.x;
  if(idx >= NLAYERS*Hh*MEMD*DKk) return;
  int layer = idx / (Hh*MEMD*DKk);
  int r = idx - layer*(Hh*MEMD*DKk);
  int h = r / (MEMD*DKk);
  int r2 = r - h*(MEMD*DKk);
  int d = r2 / DKk;
  int kk = r2 - d*DKk;
  wcat[(size_t)layer*MEMD*MEMD + (size_t)d*MEMD + h*DKk + kk] = Wh[idx];
}

// ---------------- s_i, s_j per (b,h,l) ----------------
__global__ void sisj_kernel(const float* __restrict__ proj, const float* __restrict__ awl,
                            float* __restrict__ si, float* __restrict__ sj)
{
  int idx = blockIdx.x*blockDim.x + threadIdx.x;
  if(idx >= Bb*Hh*Ll) return;
  int b = idx / (Hh*Ll);
  int r = idx - b*(Hh*Ll);
  int h = r / Ll;
  int l = r - h*Ll;
  const float* pr = proj + (((size_t)(b*Ll + l))*Hh + h)*DKk;
  const float* w1 = awl;
  const float* w2 = awl + DKk;
  float a = 0.f, c = 0.f;
  #pragma unroll
  for(int k2=0;k2<DKk;k2++){ float pv = pr[k2]; a = fmaf(pv, w1[k2], a); c = fmaf(pv, w2[k2], c); }
  si[idx] = a; sj[idx] = c;
}

// =====================================================================
// fused GAT attention: block per (b,h,half). Two-phase chunked:
//  phase1: warp-private softmax for 4 rows/warp -> Psm[32][256]
//  phase2: blocked AV GEMM (P[32x256] @ V[256x50]) with FFMA2
// smem: projS[256*50] + Psm[32*256] + sjS[256] + siS[128] = 85504 B
// =====================================================================
__global__ __launch_bounds__(256) void gat_attn_kernel(
    const float* __restrict__ proj, const float* __restrict__ si, const float* __restrict__ sj,
    const unsigned char* __restrict__ adj, const float* __restrict__ abp,
    float* __restrict__ cat)
{
  extern __shared__ float smx[];
  float* projS = smx;                   // 12800
  float* Psm   = projS + Ll*DKk;        // 8192
  float* sjS   = Psm + 32*Ll;           // 256
  float* siS   = sjS + Ll;              // 128

  int bhh = blockIdx.x;
  int bh = bhh >> 1, half = bhh & 1;
  int b = bh / Hh, h = bh - b*Hh;
  int tid = threadIdx.x;
  int lane = tid & 31, w = tid >> 5;

  // stage proj slice for this head: projS[m*50+k] (float2 loads)
  {
    const float* projBase = proj + ((size_t)(b*Ll))*MEMD + h*DKk;
    float2* dst = (float2*)projS;
    for(int e=tid; e<Ll*25; e+=256){
      int m = e / 25, t = e - m*25;
      dst[m*25+t] = ((const float2*)(projBase + (size_t)m*MEMD))[t];
    }
  }
  sjS[tid] = sj[(size_t)bh*Ll + tid];
  if(tid < 128) siS[tid] = si[(size_t)bh*Ll + half*128 + tid];
  __syncthreads();

  float abv = abp[0];
  const unsigned char* adjb = adj + (size_t)b*Ll*Ll;

  for(int c=0; c<4; c++){
    // ---- phase 1: softmax for 32 rows (warp w does rows w*4..w*4+3) ----
    #pragma unroll
    for(int rr=0; rr<4; rr++){
      int pr = w*4 + rr;
      int l = half*128 + c*32 + pr;
      float si_l = siS[c*32 + pr];
      const unsigned char* arow = adjb + (size_t)l*Ll;
      float pv[8]; bool okv[8];
      float mx = -3.0e38f;
      #pragma unroll
      for(int j=0;j<8;j++){
        int m = lane + j*32;
        float sval = si_l + sjS[m] + abv;
        sval = (sval > 0.f) ? sval : 0.2f*sval;
        bool ok = arow[m] != 0;
        okv[j] = ok; pv[j] = sval;
        mx = fmaxf(mx, ok ? sval : -3.0e38f);
      }
      #pragma unroll
      for(int o=16;o;o>>=1) mx = fmaxf(mx, __shfl_xor_sync(0xffffffffu, mx, o));
      float ev[8];
      float s = 0.f;
      #pragma unroll
      for(int j=0;j<8;j++){
        ev[j] = okv[j] ? expf(pv[j] - mx) : 0.f;
        s += ev[j];
      }
      #pragma unroll
      for(int o=16;o;o>>=1) s += __shfl_xor_sync(0xffffffffu, s, o);
      float inv = 1.0f / s;
      #pragma unroll
      for(int j=0;j<8;j++)
        Psm[pr*Ll + lane + j*32] = ev[j] * inv;
    }
    __syncthreads();

    // ---- phase 2: AV += P[32x256] @ V[256x50] ----
    if(lane < 25){
      unsigned long long acc[4] = {0ull,0ull,0ull,0ull};
      const unsigned long long* Vp = (const unsigned long long*)projS;
      #pragma unroll 4
      for(int m=0; m<Ll; m++){
        unsigned long long bv = Vp[m*25 + lane];
        #pragma unroll
        for(int t=0;t<4;t++){
          float pt = Psm[(w + 8*t)*Ll + m];
          FFMA2(acc[t], dup_f32(pt), bv);
        }
      }
      #pragma unroll
      for(int t=0;t<4;t++){
        int pr = w + 8*t;
        int l = half*128 + c*32 + pr;
        float2 o = unpack2(acc[t]);
        *(float2*)&cat[((size_t)(b*Ll + l))*MEMD + h*DKk + lane*2] = o;
      }
    }
    __syncthreads();
  }
}

// ---------------- res = h + cat; LayerNorm -> h (in place) ----------------
__global__ __launch_bounds__(256) void add_ln_kernel(
    float* __restrict__ hbuf, const float* __restrict__ cat,
    const float* __restrict__ g, const float* __restrict__ bln)
{
  __shared__ float rbuf[MEMD];
  __shared__ float red[8];
  int row = blockIdx.x, tid = threadIdx.x;
  float s = 0.f;
  for(int d=tid; d<MEMD; d+=256){
    float r = hbuf[(size_t)row*MEMD + d] + cat[(size_t)row*MEMD + d];
    rbuf[d] = r; s += r;
  }
  s = blockSum256(s, red);
  float mu = s * (1.f/MEMD);
  float v = 0.f;
  for(int d=tid; d<MEMD; d+=256){ float r = rbuf[d] - mu; v = fmaf(r, r, v); }
  v = blockSum256(v, red);
  float inv = 1.0f / sqrtf(v*(1.f/MEMD) + 1e-5f);
  for(int d=tid; d<MEMD; d+=256)
    hbuf[(size_t)row*MEMD + d] = (rbuf[d] - mu) * inv * g[d] + bln[d];
}

// ---------------- pooled = mean_l h; out = pooled @ Wc + bc ----------------
__global__ __launch_bounds__(256) void pool_classify_kernel(
    const float* __restrict__ hbuf, const float* __restrict__ Wc,
    const float* __restrict__ bc, float* __restrict__ out)
{
  __shared__ float pooled[MEMD];
  __shared__ float red[8];
  int b = blockIdx.x, tid = threadIdx.x;
  for(int d=tid; d<MEMD; d+=256){
    float s = 0.f;
    for(int l=0; l<Ll; l++) s += hbuf[((size_t)(b*Ll + l))*MEMD + d];
    pooled[d] = s * (1.f/Ll);
  }
  __syncthreads();
  for(int c=0; c<NCc; c++){
    float p = 0.f;
    for(int d=tid; d<MEMD; d+=256) p = fmaf(pooled[d], Wc[d*NCc + c], p);
    p = blockSum256(p, red);
    if(tid == 0) out[b*NCc + c] = p + bc[c];
  }
}

// ---------------- launcher ----------------
extern "C" void kernel_launch(void* const* d_in, const int* in_sizes, int n_in,
                              void* d_out, int out_size)
{
  const float* x    = (const float*)d_in[0];
  const float* wq   = (const float*)d_in[1];
  const float* bq   = (const float*)d_in[2];
  const float* wk   = (const float*)d_in[3];
  const float* bk   = (const float*)d_in[4];
  const float* w_in = (const float*)d_in[5];
  const float* b_in = (const float*)d_in[6];
  const float* Wh   = (const float*)d_in[7];
  const float* bh   = (const float*)d_in[8];
  const float* aw   = (const float*)d_in[9];
  const float* ab   = (const float*)d_in[10];
  const float* g_ln = (const float*)d_in[11];
  const float* b_ln = (const float*)d_in[12];
  const float* Wc   = (const float*)d_in[13];
  const float* bc   = (const float*)d_in[14];
  float* out = (float*)d_out;

  float *pq, *pk, *pscores, *ppattn, *pkth, *ph, *pproj, *pcat, *psi, *psj, *pwcat;
  unsigned char* padj;
  cudaGetSymbolAddress((void**)&pq, g_q);
  cudaGetSymbolAddress((void**)&pk, g_k);
  cudaGetSymbolAddress((void**)&pscores, g_scores);
  cudaGetSymbolAddress((void**)&ppattn, g_pattn);
  cudaGetSymbolAddress((void**)&pkth, g_kth);
  cudaGetSymbolAddress((void**)&padj, g_adj);
  cudaGetSymbolAddress((void**)&ph, g_h);
  cudaGetSymbolAddress((void**)&pproj, g_proj);
  cudaGetSymbolAddress((void**)&pcat, g_cat);
  cudaGetSymbolAddress((void**)&psi, g_si);
  cudaGetSymbolAddress((void**)&psj, g_sj);
  cudaGetSymbolAddress((void**)&pwcat, g_wcat);

  const int ATTN_SMEM = (Ll*DKk + 32*Ll + Ll + 128) * 4; // 85504 bytes
  cudaFuncSetAttribute(gat_attn_kernel, cudaFuncAttributeMaxDynamicSharedMemorySize, ATTN_SMEM);
  cudaFuncSetAttribute(gemm_tf32x3, cudaFuncAttributeMaxDynamicSharedMemorySize, GEMM_SMEM);

  // q, k projections (3xTF32 tensor core)
  gemm_tf32x3<<<dim3(DIN/128, BL/128), 256, GEMM_SMEM>>>(x, wq, bq, pq, BL, DIN, DIN);
  gemm_tf32x3<<<dim3(DIN/128, BL/128), 256, GEMM_SMEM>>>(x, wk, bk, pk, BL, DIN, DIN);

  // scores + softmax + head-mean
  qk_scores128<<<dim3(2, 2, Bb*Hh), 256>>>(pq, pk, pscores);
  softmax_mean_kernel<<<Bb*Ll, 256>>>(pscores, ppattn);

  // top-k threshold + adjacency
  topk_select_kernel<<<Bb, 1024>>>(ppattn, pkth);
  build_adj_kernel<<<Bb*Ll, 256>>>(ppattn, pkth, padj);

  // h = x @ w_in + b_in (3xTF32)
  gemm_tf32x3<<<dim3((MEMD+127)/128, BL/128), 256, GEMM_SMEM>>>(x, w_in, b_in, ph, BL, MEMD, DIN);

  // repack Wh into (layer, MEM, H*DK)
  repack_wh_kernel<<<(NLAYERS*Hh*MEMD*DKk + 255)/256, 256>>>(Wh, pwcat);

  for(int layer=0; layer<NLAYERS; layer++){
    gemm_tf32x3<<<dim3((MEMD+127)/128, BL/128), 256, GEMM_SMEM>>>(
        ph, pwcat + (size_t)layer*MEMD*MEMD, bh + layer*MEMD, pproj, BL, MEMD, MEMD);
    sisj_kernel<<<(Bb*Hh*Ll + 127)/128, 128>>>(pproj, aw + layer*2*DKk, psi, psj);
    gat_attn_kernel<<<Bb*Hh*2, 256, ATTN_SMEM>>>(pproj, psi, psj, padj, ab + layer, pcat);
    add_ln_kernel<<<Bb*Ll, 256>>>(ph, pcat, g_ln + layer*MEMD, b_ln + layer*MEMD);
  }

  pool_classify_kernel<<<Bb, 256>>>(ph, Wc, bc, out);
}